// round 1
// baseline (speedup 1.0000x reference)
#include <cuda_runtime.h>
#include <cuda_bf16.h>
#include <math.h>

#define NN 50000
#define EE 400000
#define E2 (EE + NN)
#define OUTD 16

// ---------------- scratch (device globals; no allocs allowed) ----------------
__device__ __align__(16) float g_xl1[NN * 256];
__device__ __align__(16) float g_xr1[NN * 256];
__device__ __align__(16) float g_h1[NN * 256];
__device__ __align__(16) float g_e1[E2 * 4];
__device__ __align__(16) float g_xl2[NN * OUTD];
__device__ __align__(16) float g_xr2[NN * OUTD];
__device__ int g_esrc[E2];
__device__ int g_counts[NN];
__device__ int g_fill[NN];
__device__ int g_rowptr[NN + 1];
__device__ __align__(16) float g_Wcat1[256 * 512];
__device__ __align__(16) float g_bcat1[512];
__device__ __align__(16) float g_Wcat2[256 * 32];
__device__ __align__(16) float g_bcat2[32];

// ---------------- f32x2 packed math helpers ----------------
__device__ __forceinline__ unsigned long long pk2(float x, float y) {
    unsigned long long r;
    asm("mov.b64 %0, {%1, %2};" : "=l"(r) : "f"(x), "f"(y));
    return r;
}
__device__ __forceinline__ unsigned long long fma2(unsigned long long a,
                                                   unsigned long long b,
                                                   unsigned long long c) {
    unsigned long long d;
    asm("fma.rn.f32x2 %0, %1, %2, %3;" : "=l"(d) : "l"(a), "l"(b), "l"(c));
    return d;
}
__device__ __forceinline__ float2 upk2(unsigned long long v) {
    float2 f;
    asm("mov.b64 {%0, %1}, %2;" : "=f"(f.x), "=f"(f.y) : "l"(v));
    return f;
}

__device__ __forceinline__ float lrelu(float v) { return v > 0.f ? v : 0.2f * v; }

// ---------------- init ----------------
__global__ void k_zero() {
    int i = blockIdx.x * blockDim.x + threadIdx.x;
    if (i < NN) { g_counts[i] = 0; g_fill[i] = 0; }
}

// pack [Wl|Wr] and [bl|br] for both layers
__global__ void k_prep(const float* __restrict__ Wl1, const float* __restrict__ bl1,
                       const float* __restrict__ Wr1, const float* __restrict__ br1,
                       const float* __restrict__ Wl2, const float* __restrict__ bl2,
                       const float* __restrict__ Wr2, const float* __restrict__ br2) {
    for (int i = blockIdx.x * blockDim.x + threadIdx.x; i < 256 * 512;
         i += gridDim.x * blockDim.x) {
        int k = i >> 9, n = i & 511;
        g_Wcat1[i] = (n < 256) ? Wl1[k * 256 + n] : Wr1[k * 256 + (n - 256)];
        if (i < 512) g_bcat1[i] = (i < 256) ? bl1[i] : br1[i - 256];
        if (i < 256 * 32) {
            int k2 = i >> 5, n2 = i & 31;
            g_Wcat2[i] = (n2 < 16) ? Wl2[k2 * 16 + n2] : Wr2[k2 * 16 + (n2 - 16)];
        }
        if (i < 32) g_bcat2[i] = (i < 16) ? bl2[i] : br2[i - 16];
    }
}

// ---------------- CSR build (dst-sorted) ----------------
__global__ void k_hist(const int* __restrict__ ei) {
    int i = blockIdx.x * blockDim.x + threadIdx.x;
    if (i >= E2) return;
    int dd = (i < EE) ? ei[EE + i] : (i - EE);
    atomicAdd(&g_counts[dd], 1);
}

__global__ void k_scan() {
    __shared__ int sh[1024];
    __shared__ int s_off;
    int tid = threadIdx.x;
    if (tid == 0) s_off = 0;
    __syncthreads();
    for (int base = 0; base < NN; base += 1024) {
        int i = base + tid;
        int v = (i < NN) ? g_counts[i] : 0;
        sh[tid] = v;
        __syncthreads();
        for (int st = 1; st < 1024; st <<= 1) {
            int a = (tid >= st) ? sh[tid - st] : 0;
            __syncthreads();
            sh[tid] += a;
            __syncthreads();
        }
        if (i < NN) g_rowptr[i] = s_off + sh[tid] - v;
        int tot = sh[1023];
        __syncthreads();
        if (tid == 0) s_off += tot;
        __syncthreads();
    }
    if (tid == 0) g_rowptr[NN] = s_off;
}

__global__ void k_scatter(const int* __restrict__ ei) {
    int i = blockIdx.x * blockDim.x + threadIdx.x;
    if (i >= E2) return;
    int s  = (i < EE) ? ei[i]      : (i - EE);
    int dd = (i < EE) ? ei[EE + i] : (i - EE);
    int pos = g_rowptr[dd] + atomicAdd(&g_fill[dd], 1);
    g_esrc[pos] = s;
}

// ---------------- GEMM1: X[50000,256] @ Wcat1[256,512] -> xl1|xr1 ----------------
// 128x64 block tile, BK=16, 256 threads, 8x4 thread tile via f32x2 FMAs.
__global__ void k_gemm1(const float* __restrict__ X) {
    __shared__ __align__(16) float As[16][128];  // [k][m]
    __shared__ __align__(16) float Bs[16][64];   // [k][n]
    int t = threadIdx.x;
    int m0 = blockIdx.x * 128;
    int n0 = blockIdx.y * 64;
    int tm = t >> 4;   // 0..15 -> rows tm*8..tm*8+7
    int tn = t & 15;   // 0..15 -> cols tn*4..tn*4+3

    unsigned long long acc[8][2];
#pragma unroll
    for (int i = 0; i < 8; i++) { acc[i][0] = 0ull; acc[i][1] = 0ull; }

    for (int k0 = 0; k0 < 256; k0 += 16) {
        // A tile: 128 rows x 16 cols = 512 float4; 2 per thread, store transposed
#pragma unroll
        for (int q = 0; q < 2; q++) {
            int idx = t * 2 + q;
            int row = idx >> 2, c4 = idx & 3;
            int gm = m0 + row;
            float4 v = make_float4(0.f, 0.f, 0.f, 0.f);
            if (gm < NN) v = *(const float4*)(X + (size_t)gm * 256 + k0 + c4 * 4);
            As[c4 * 4 + 0][row] = v.x;
            As[c4 * 4 + 1][row] = v.y;
            As[c4 * 4 + 2][row] = v.z;
            As[c4 * 4 + 3][row] = v.w;
        }
        // B tile: 16 x 64 = 256 float4; 1 per thread
        {
            int kk = t >> 4, nq = t & 15;
            float4 v = *(const float4*)(g_Wcat1 + (size_t)(k0 + kk) * 512 + n0 + nq * 4);
            *(float4*)&Bs[kk][nq * 4] = v;
        }
        __syncthreads();
#pragma unroll
        for (int kk = 0; kk < 16; kk++) {
            float4 a0 = *(const float4*)&As[kk][tm * 8];
            float4 a1 = *(const float4*)&As[kk][tm * 8 + 4];
            float4 bv = *(const float4*)&Bs[kk][tn * 4];
            unsigned long long b01 = pk2(bv.x, bv.y);
            unsigned long long b23 = pk2(bv.z, bv.w);
            float ar[8] = {a0.x, a0.y, a0.z, a0.w, a1.x, a1.y, a1.z, a1.w};
#pragma unroll
            for (int i = 0; i < 8; i++) {
                unsigned long long a2 = pk2(ar[i], ar[i]);
                acc[i][0] = fma2(a2, b01, acc[i][0]);
                acc[i][1] = fma2(a2, b23, acc[i][1]);
            }
        }
        __syncthreads();
    }
    // epilogue
    bool isR = (n0 >= 256);
    float* Out = isR ? g_xr1 : g_xl1;
    int ncol = n0 - (isR ? 256 : 0) + tn * 4;
    float bb0 = g_bcat1[n0 + tn * 4 + 0];
    float bb1 = g_bcat1[n0 + tn * 4 + 1];
    float bb2 = g_bcat1[n0 + tn * 4 + 2];
    float bb3 = g_bcat1[n0 + tn * 4 + 3];
#pragma unroll
    for (int i = 0; i < 8; i++) {
        int gm = m0 + tm * 8 + i;
        if (gm < NN) {
            float2 p0 = upk2(acc[i][0]);
            float2 p1 = upk2(acc[i][1]);
            float4 r = make_float4(p0.x + bb0, p0.y + bb1, p1.x + bb2, p1.y + bb3);
            *(float4*)(Out + (size_t)gm * 256 + ncol) = r;
        }
    }
}

// ---------------- layer-1 edge phase: warp per dst node ----------------
__global__ void k_edge1(const float* __restrict__ att1, const float* __restrict__ bias1) {
    int gw = (blockIdx.x * blockDim.x + threadIdx.x) >> 5;
    int lane = threadIdx.x & 31;
    if (gw >= NN) return;
    int d = gw;
    int cb = lane * 8;  // 8 channels per lane; head = lane>>3 (64 ch per head)
    const float4* xrp = (const float4*)(g_xr1 + (size_t)d * 256 + cb);
    float4 xr0 = xrp[0], xr1v = xrp[1];
    const float4* ap = (const float4*)(att1 + cb);
    float4 at0 = ap[0], at1 = ap[1];
    int p0 = g_rowptr[d], p1 = g_rowptr[d + 1];
    int head = lane >> 3;

    float maxe = -INFINITY;
    for (int p = p0; p < p1; p++) {
        int s = g_esrc[p];
        const float4* xs = (const float4*)(g_xl1 + (size_t)s * 256 + cb);
        float4 a0 = xs[0], a1 = xs[1];
        float pa = lrelu(a0.x + xr0.x) * at0.x + lrelu(a0.y + xr0.y) * at0.y +
                   lrelu(a0.z + xr0.z) * at0.z + lrelu(a0.w + xr0.w) * at0.w +
                   lrelu(a1.x + xr1v.x) * at1.x + lrelu(a1.y + xr1v.y) * at1.y +
                   lrelu(a1.z + xr1v.z) * at1.z + lrelu(a1.w + xr1v.w) * at1.w;
        pa += __shfl_xor_sync(0xffffffffu, pa, 1);
        pa += __shfl_xor_sync(0xffffffffu, pa, 2);
        pa += __shfl_xor_sync(0xffffffffu, pa, 4);
        if ((lane & 7) == 0) g_e1[(size_t)p * 4 + head] = pa;
        maxe = fmaxf(maxe, pa);
    }
    __threadfence_block();
    __syncwarp();

    float4 acc0 = make_float4(0.f, 0.f, 0.f, 0.f), acc1 = acc0;
    float denom = 0.f;
    for (int p = p0; p < p1; p++) {
        int s = g_esrc[p];
        float ee = __expf(g_e1[(size_t)p * 4 + head] - maxe);
        denom += ee;
        const float4* xs = (const float4*)(g_xl1 + (size_t)s * 256 + cb);
        float4 a0 = xs[0], a1 = xs[1];
        acc0.x += ee * a0.x; acc0.y += ee * a0.y; acc0.z += ee * a0.z; acc0.w += ee * a0.w;
        acc1.x += ee * a1.x; acc1.y += ee * a1.y; acc1.z += ee * a1.z; acc1.w += ee * a1.w;
    }
    float inv = 1.f / (denom + 1e-16f);
    const float4* bp = (const float4*)(bias1 + cb);
    float4 b0 = bp[0], b1 = bp[1];
    float4 o0, o1;
    o0.x = tanhf(acc0.x * inv + b0.x); o0.y = tanhf(acc0.y * inv + b0.y);
    o0.z = tanhf(acc0.z * inv + b0.z); o0.w = tanhf(acc0.w * inv + b0.w);
    o1.x = tanhf(acc1.x * inv + b1.x); o1.y = tanhf(acc1.y * inv + b1.y);
    o1.z = tanhf(acc1.z * inv + b1.z); o1.w = tanhf(acc1.w * inv + b1.w);
    float4* hp = (float4*)(g_h1 + (size_t)d * 256 + cb);
    hp[0] = o0; hp[1] = o1;
}

// ---------------- GEMM2: h1[50000,256] @ Wcat2[256,32] -> xl2|xr2 ----------------
__global__ void k_gemm2() {
    __shared__ float Ws[256 * 32];
    int t = threadIdx.x;
    for (int i = t; i < 256 * 32; i += 256) Ws[i] = g_Wcat2[i];
    __syncthreads();
    int warp = t >> 5, lane = t & 31;
    int row = blockIdx.x * 8 + warp;
    if (row >= NN) return;
    float acc = 0.f;
    const float* hrow = g_h1 + (size_t)row * 256;
    for (int k0 = 0; k0 < 256; k0 += 32) {
        float hv = hrow[k0 + lane];
#pragma unroll
        for (int j = 0; j < 32; j++) {
            float hb = __shfl_sync(0xffffffffu, hv, j);
            acc += hb * Ws[(k0 + j) * 32 + lane];
        }
    }
    float v = acc + g_bcat2[lane];
    if (lane < 16) g_xl2[(size_t)row * 16 + lane] = v;
    else           g_xr2[(size_t)row * 16 + (lane - 16)] = v;
}

// ---------------- layer-2 edge phase + log_softmax: warp per dst node ----------------
__global__ void k_edge2(const float* __restrict__ att2, const float* __restrict__ bias2,
                        float* __restrict__ outO, float* __restrict__ outLP) {
    int gw = (blockIdx.x * blockDim.x + threadIdx.x) >> 5;
    int lane = threadIdx.x & 31;
    if (gw >= NN) return;
    int d = gw;
    int c = lane & 15;  // both 16-lane halves mirror the same work
    float xrv = g_xr2[(size_t)d * 16 + c];
    float av = att2[c];
    int p0 = g_rowptr[d], p1 = g_rowptr[d + 1];

    float maxe = -INFINITY;
    for (int p = p0; p < p1; p++) {
        int s = g_esrc[p];
        float v = g_xl2[(size_t)s * 16 + c] + xrv;
        v = v > 0.f ? v : 0.2f * v;
        float pa = v * av;
        pa += __shfl_xor_sync(0xffffffffu, pa, 1);
        pa += __shfl_xor_sync(0xffffffffu, pa, 2);
        pa += __shfl_xor_sync(0xffffffffu, pa, 4);
        pa += __shfl_xor_sync(0xffffffffu, pa, 8);
        if (lane == 0) g_e1[p] = pa;
        maxe = fmaxf(maxe, pa);
    }
    __threadfence_block();
    __syncwarp();

    float acc = 0.f, denom = 0.f;
    for (int p = p0; p < p1; p++) {
        int s = g_esrc[p];
        float ee = __expf(g_e1[p] - maxe);
        denom += ee;
        acc += ee * g_xl2[(size_t)s * 16 + c];
    }
    float o = acc / (denom + 1e-16f) + bias2[c];

    // log_softmax over the 16 channels
    float m = o;
    m = fmaxf(m, __shfl_xor_sync(0xffffffffu, m, 1));
    m = fmaxf(m, __shfl_xor_sync(0xffffffffu, m, 2));
    m = fmaxf(m, __shfl_xor_sync(0xffffffffu, m, 4));
    m = fmaxf(m, __shfl_xor_sync(0xffffffffu, m, 8));
    float se = __expf(o - m);
    se += __shfl_xor_sync(0xffffffffu, se, 1);
    se += __shfl_xor_sync(0xffffffffu, se, 2);
    se += __shfl_xor_sync(0xffffffffu, se, 4);
    se += __shfl_xor_sync(0xffffffffu, se, 8);
    float lp = o - m - logf(se);

    if (lane < 16) {
        outO[(size_t)d * 16 + c] = o;
        if (outLP) outLP[(size_t)d * 16 + c] = lp;
    }
}

// ---------------- launch ----------------
extern "C" void kernel_launch(void* const* d_in, const int* in_sizes, int n_in,
                              void* d_out, int out_size) {
    const float* x     = (const float*)d_in[0];
    const int*   ei    = (const int*)d_in[1];
    const float* Wl1   = (const float*)d_in[2];
    const float* bl1   = (const float*)d_in[3];
    const float* Wr1   = (const float*)d_in[4];
    const float* br1   = (const float*)d_in[5];
    const float* att1  = (const float*)d_in[6];
    const float* bias1 = (const float*)d_in[7];
    const float* Wl2   = (const float*)d_in[8];
    const float* bl2   = (const float*)d_in[9];
    const float* Wr2   = (const float*)d_in[10];
    const float* br2   = (const float*)d_in[11];
    const float* att2  = (const float*)d_in[12];
    const float* bias2 = (const float*)d_in[13];

    float* outO  = (float*)d_out;
    float* outLP = (out_size >= 2 * NN * OUTD) ? ((float*)d_out + NN * OUTD) : nullptr;

    k_zero<<<(NN + 255) / 256, 256>>>();
    k_prep<<<512, 256>>>(Wl1, bl1, Wr1, br1, Wl2, bl2, Wr2, br2);
    k_hist<<<(E2 + 255) / 256, 256>>>(ei);
    k_scan<<<1, 1024>>>();
    k_scatter<<<(E2 + 255) / 256, 256>>>(ei);

    dim3 g1((NN + 127) / 128, 8);
    k_gemm1<<<g1, 256>>>(x);
    k_edge1<<<(NN + 7) / 8, 256>>>(att1, bias1);
    k_gemm2<<<(NN + 7) / 8, 256>>>();
    k_edge2<<<(NN + 7) / 8, 256>>>(att2, bias2, outO, outLP);
}

// round 2
// speedup vs baseline: 1.1086x; 1.1086x over previous
#include <cuda_runtime.h>
#include <cuda_bf16.h>
#include <math.h>

#define NN 50000
#define EE 400000
#define E2 (EE + NN)
#define OUTD 16

// ---------------- scratch (device globals; no allocs allowed) ----------------
__device__ __align__(16) float g_xl1[NN * 256];
__device__ __align__(16) float g_xr1[NN * 256];
__device__ __align__(16) float g_h1[NN * 256];
__device__ __align__(16) float g_e1[E2 * 4];
__device__ __align__(16) float g_xl2[NN * OUTD];
__device__ __align__(16) float g_xr2[NN * OUTD];
__device__ int g_esrc[E2];
__device__ int g_counts[NN];
__device__ int g_fill[NN];
__device__ int g_rowptr[NN + 1];
__device__ int g_bsum[64];
__device__ int g_boff[64];
__device__ __align__(16) float g_Wcat1[256 * 512];
__device__ __align__(16) float g_bcat1[512];
__device__ __align__(16) float g_Wcat2[256 * 32];
__device__ __align__(16) float g_bcat2[32];

// ---------------- f32x2 packed math helpers ----------------
__device__ __forceinline__ unsigned long long pk2(float x, float y) {
    unsigned long long r;
    asm("mov.b64 %0, {%1, %2};" : "=l"(r) : "f"(x), "f"(y));
    return r;
}
__device__ __forceinline__ unsigned long long fma2(unsigned long long a,
                                                   unsigned long long b,
                                                   unsigned long long c) {
    unsigned long long d;
    asm("fma.rn.f32x2 %0, %1, %2, %3;" : "=l"(d) : "l"(a), "l"(b), "l"(c));
    return d;
}
__device__ __forceinline__ float2 upk2(unsigned long long v) {
    float2 f;
    asm("mov.b64 {%0, %1}, %2;" : "=f"(f.x), "=f"(f.y) : "l"(v));
    return f;
}

__device__ __forceinline__ float lrelu(float v) { return v > 0.f ? v : 0.2f * v; }

// ---------------- init ----------------
__global__ void k_zero() {
    int i = blockIdx.x * blockDim.x + threadIdx.x;
    if (i < NN) { g_counts[i] = 0; g_fill[i] = 0; }
}

// pack [Wl|Wr] and [bl|br] for both layers
__global__ void k_prep(const float* __restrict__ Wl1, const float* __restrict__ bl1,
                       const float* __restrict__ Wr1, const float* __restrict__ br1,
                       const float* __restrict__ Wl2, const float* __restrict__ bl2,
                       const float* __restrict__ Wr2, const float* __restrict__ br2) {
    for (int i = blockIdx.x * blockDim.x + threadIdx.x; i < 256 * 512;
         i += gridDim.x * blockDim.x) {
        int k = i >> 9, n = i & 511;
        g_Wcat1[i] = (n < 256) ? Wl1[k * 256 + n] : Wr1[k * 256 + (n - 256)];
        if (i < 512) g_bcat1[i] = (i < 256) ? bl1[i] : br1[i - 256];
        if (i < 256 * 32) {
            int k2 = i >> 5, n2 = i & 31;
            g_Wcat2[i] = (n2 < 16) ? Wl2[k2 * 16 + n2] : Wr2[k2 * 16 + (n2 - 16)];
        }
        if (i < 32) g_bcat2[i] = (i < 16) ? bl2[i] : br2[i - 16];
    }
}

// ---------------- CSR build (dst-sorted) ----------------
__global__ void k_hist(const int* __restrict__ ei) {
    int i = blockIdx.x * blockDim.x + threadIdx.x;
    if (i >= E2) return;
    int dd = (i < EE) ? ei[EE + i] : (i - EE);
    atomicAdd(&g_counts[dd], 1);
}

// --- 3-phase grid-wide exclusive scan of g_counts -> g_rowptr ---
#define SCAN_BLOCKS 49

__global__ void k_scan1() {
    __shared__ int wsum[32];
    int tid = threadIdx.x;
    int lane = tid & 31, w = tid >> 5;
    int i = blockIdx.x * 1024 + tid;
    int v = (i < NN) ? g_counts[i] : 0;
    // warp inclusive scan
    int x = v;
#pragma unroll
    for (int st = 1; st < 32; st <<= 1) {
        int y = __shfl_up_sync(0xffffffffu, x, st);
        if (lane >= st) x += y;
    }
    if (lane == 31) wsum[w] = x;
    __syncthreads();
    if (w == 0) {
        int s = wsum[lane];
#pragma unroll
        for (int st = 1; st < 32; st <<= 1) {
            int y = __shfl_up_sync(0xffffffffu, s, st);
            if (lane >= st) s += y;
        }
        wsum[lane] = s;  // inclusive warp sums
    }
    __syncthreads();
    int off = (w > 0) ? wsum[w - 1] : 0;
    int incl = x + off;
    if (i < NN) g_rowptr[i] = incl - v;  // block-local exclusive
    if (tid == 1023) g_bsum[blockIdx.x] = incl;
}

__global__ void k_scan2() {
    if (threadIdx.x == 0) {
        int acc = 0;
        for (int b = 0; b < SCAN_BLOCKS; b++) {
            g_boff[b] = acc;
            acc += g_bsum[b];
        }
        g_rowptr[NN] = acc;
    }
}

__global__ void k_scan3() {
    int i = blockIdx.x * 1024 + threadIdx.x;
    int off = g_boff[blockIdx.x];
    if (i < NN && blockIdx.x > 0) g_rowptr[i] += off;
}

__global__ void k_scatter(const int* __restrict__ ei) {
    int i = blockIdx.x * blockDim.x + threadIdx.x;
    if (i >= E2) return;
    int s  = (i < EE) ? ei[i]      : (i - EE);
    int dd = (i < EE) ? ei[EE + i] : (i - EE);
    int pos = g_rowptr[dd] + atomicAdd(&g_fill[dd], 1);
    g_esrc[pos] = s;
}

// ---------------- GEMM1: X[50000,256] @ Wcat1[256,512] -> xl1|xr1 ----------------
// 128x64 block tile, BK=16, 256 threads, 8x4 thread tile via f32x2 FMAs.
__global__ void k_gemm1(const float* __restrict__ X) {
    __shared__ __align__(16) float As[16][128];  // [k][m]
    __shared__ __align__(16) float Bs[16][64];   // [k][n]
    int t = threadIdx.x;
    int m0 = blockIdx.x * 128;
    int n0 = blockIdx.y * 64;
    int tm = t >> 4;   // 0..15 -> rows tm*8..tm*8+7
    int tn = t & 15;   // 0..15 -> cols tn*4..tn*4+3

    unsigned long long acc[8][2];
#pragma unroll
    for (int i = 0; i < 8; i++) { acc[i][0] = 0ull; acc[i][1] = 0ull; }

    for (int k0 = 0; k0 < 256; k0 += 16) {
        // A tile: 128 rows x 16 cols = 512 float4; 2 per thread, store transposed
#pragma unroll
        for (int q = 0; q < 2; q++) {
            int idx = t * 2 + q;
            int row = idx >> 2, c4 = idx & 3;
            int gm = m0 + row;
            float4 v = make_float4(0.f, 0.f, 0.f, 0.f);
            if (gm < NN) v = *(const float4*)(X + (size_t)gm * 256 + k0 + c4 * 4);
            As[c4 * 4 + 0][row] = v.x;
            As[c4 * 4 + 1][row] = v.y;
            As[c4 * 4 + 2][row] = v.z;
            As[c4 * 4 + 3][row] = v.w;
        }
        // B tile: 16 x 64 = 256 float4; 1 per thread
        {
            int kk = t >> 4, nq = t & 15;
            float4 v = *(const float4*)(g_Wcat1 + (size_t)(k0 + kk) * 512 + n0 + nq * 4);
            *(float4*)&Bs[kk][nq * 4] = v;
        }
        __syncthreads();
#pragma unroll
        for (int kk = 0; kk < 16; kk++) {
            float4 a0 = *(const float4*)&As[kk][tm * 8];
            float4 a1 = *(const float4*)&As[kk][tm * 8 + 4];
            float4 bv = *(const float4*)&Bs[kk][tn * 4];
            unsigned long long b01 = pk2(bv.x, bv.y);
            unsigned long long b23 = pk2(bv.z, bv.w);
            float ar[8] = {a0.x, a0.y, a0.z, a0.w, a1.x, a1.y, a1.z, a1.w};
#pragma unroll
            for (int i = 0; i < 8; i++) {
                unsigned long long a2 = pk2(ar[i], ar[i]);
                acc[i][0] = fma2(a2, b01, acc[i][0]);
                acc[i][1] = fma2(a2, b23, acc[i][1]);
            }
        }
        __syncthreads();
    }
    // epilogue
    bool isR = (n0 >= 256);
    float* Out = isR ? g_xr1 : g_xl1;
    int ncol = n0 - (isR ? 256 : 0) + tn * 4;
    float bb0 = g_bcat1[n0 + tn * 4 + 0];
    float bb1 = g_bcat1[n0 + tn * 4 + 1];
    float bb2 = g_bcat1[n0 + tn * 4 + 2];
    float bb3 = g_bcat1[n0 + tn * 4 + 3];
#pragma unroll
    for (int i = 0; i < 8; i++) {
        int gm = m0 + tm * 8 + i;
        if (gm < NN) {
            float2 p0 = upk2(acc[i][0]);
            float2 p1 = upk2(acc[i][1]);
            float4 r = make_float4(p0.x + bb0, p0.y + bb1, p1.x + bb2, p1.y + bb3);
            *(float4*)(Out + (size_t)gm * 256 + ncol) = r;
        }
    }
}

// ---------------- layer-1 edge phase: warp per dst node ----------------
__global__ void k_edge1(const float* __restrict__ att1, const float* __restrict__ bias1) {
    int gw = (blockIdx.x * blockDim.x + threadIdx.x) >> 5;
    int lane = threadIdx.x & 31;
    if (gw >= NN) return;
    int d = gw;
    int cb = lane * 8;  // 8 channels per lane; head = lane>>3 (64 ch per head)
    const float4* xrp = (const float4*)(g_xr1 + (size_t)d * 256 + cb);
    float4 xr0 = xrp[0], xr1v = xrp[1];
    const float4* ap = (const float4*)(att1 + cb);
    float4 at0 = ap[0], at1 = ap[1];
    int p0 = g_rowptr[d], p1 = g_rowptr[d + 1];
    int head = lane >> 3;

    float maxe = -INFINITY;
    for (int p = p0; p < p1; p++) {
        int s = g_esrc[p];
        const float4* xs = (const float4*)(g_xl1 + (size_t)s * 256 + cb);
        float4 a0 = xs[0], a1 = xs[1];
        float pa = lrelu(a0.x + xr0.x) * at0.x + lrelu(a0.y + xr0.y) * at0.y +
                   lrelu(a0.z + xr0.z) * at0.z + lrelu(a0.w + xr0.w) * at0.w +
                   lrelu(a1.x + xr1v.x) * at1.x + lrelu(a1.y + xr1v.y) * at1.y +
                   lrelu(a1.z + xr1v.z) * at1.z + lrelu(a1.w + xr1v.w) * at1.w;
        pa += __shfl_xor_sync(0xffffffffu, pa, 1);
        pa += __shfl_xor_sync(0xffffffffu, pa, 2);
        pa += __shfl_xor_sync(0xffffffffu, pa, 4);
        if ((lane & 7) == 0) g_e1[(size_t)p * 4 + head] = pa;
        maxe = fmaxf(maxe, pa);
    }
    __threadfence_block();
    __syncwarp();

    float4 acc0 = make_float4(0.f, 0.f, 0.f, 0.f), acc1 = acc0;
    float denom = 0.f;
    for (int p = p0; p < p1; p++) {
        int s = g_esrc[p];
        float ee = __expf(g_e1[(size_t)p * 4 + head] - maxe);
        denom += ee;
        const float4* xs = (const float4*)(g_xl1 + (size_t)s * 256 + cb);
        float4 a0 = xs[0], a1 = xs[1];
        acc0.x += ee * a0.x; acc0.y += ee * a0.y; acc0.z += ee * a0.z; acc0.w += ee * a0.w;
        acc1.x += ee * a1.x; acc1.y += ee * a1.y; acc1.z += ee * a1.z; acc1.w += ee * a1.w;
    }
    float inv = 1.f / (denom + 1e-16f);
    const float4* bp = (const float4*)(bias1 + cb);
    float4 b0 = bp[0], b1 = bp[1];
    float4 o0, o1;
    o0.x = tanhf(acc0.x * inv + b0.x); o0.y = tanhf(acc0.y * inv + b0.y);
    o0.z = tanhf(acc0.z * inv + b0.z); o0.w = tanhf(acc0.w * inv + b0.w);
    o1.x = tanhf(acc1.x * inv + b1.x); o1.y = tanhf(acc1.y * inv + b1.y);
    o1.z = tanhf(acc1.z * inv + b1.z); o1.w = tanhf(acc1.w * inv + b1.w);
    float4* hp = (float4*)(g_h1 + (size_t)d * 256 + cb);
    hp[0] = o0; hp[1] = o1;
}

// ---------------- GEMM2: h1[50000,256] @ Wcat2[256,32] -> xl2|xr2 ----------------
__global__ void k_gemm2() {
    __shared__ float Ws[256 * 32];
    int t = threadIdx.x;
    for (int i = t; i < 256 * 32; i += 256) Ws[i] = g_Wcat2[i];
    __syncthreads();
    int warp = t >> 5, lane = t & 31;
    int row = blockIdx.x * 8 + warp;
    if (row >= NN) return;
    float acc = 0.f;
    const float* hrow = g_h1 + (size_t)row * 256;
    for (int k0 = 0; k0 < 256; k0 += 32) {
        float hv = hrow[k0 + lane];
#pragma unroll
        for (int j = 0; j < 32; j++) {
            float hb = __shfl_sync(0xffffffffu, hv, j);
            acc += hb * Ws[(k0 + j) * 32 + lane];
        }
    }
    float v = acc + g_bcat2[lane];
    if (lane < 16) g_xl2[(size_t)row * 16 + lane] = v;
    else           g_xr2[(size_t)row * 16 + (lane - 16)] = v;
}

// ---------------- layer-2 edge phase + log_softmax: warp per dst node ----------------
__global__ void k_edge2(const float* __restrict__ att2, const float* __restrict__ bias2,
                        float* __restrict__ outO, float* __restrict__ outLP) {
    int gw = (blockIdx.x * blockDim.x + threadIdx.x) >> 5;
    int lane = threadIdx.x & 31;
    if (gw >= NN) return;
    int d = gw;
    int c = lane & 15;  // both 16-lane halves mirror the same work
    float xrv = g_xr2[(size_t)d * 16 + c];
    float av = att2[c];
    int p0 = g_rowptr[d], p1 = g_rowptr[d + 1];

    float maxe = -INFINITY;
    for (int p = p0; p < p1; p++) {
        int s = g_esrc[p];
        float v = g_xl2[(size_t)s * 16 + c] + xrv;
        v = v > 0.f ? v : 0.2f * v;
        float pa = v * av;
        pa += __shfl_xor_sync(0xffffffffu, pa, 1);
        pa += __shfl_xor_sync(0xffffffffu, pa, 2);
        pa += __shfl_xor_sync(0xffffffffu, pa, 4);
        pa += __shfl_xor_sync(0xffffffffu, pa, 8);
        if (lane == 0) g_e1[p] = pa;
        maxe = fmaxf(maxe, pa);
    }
    __threadfence_block();
    __syncwarp();

    float acc = 0.f, denom = 0.f;
    for (int p = p0; p < p1; p++) {
        int s = g_esrc[p];
        float ee = __expf(g_e1[p] - maxe);
        denom += ee;
        acc += ee * g_xl2[(size_t)s * 16 + c];
    }
    float o = acc / (denom + 1e-16f) + bias2[c];

    // log_softmax over the 16 channels
    float m = o;
    m = fmaxf(m, __shfl_xor_sync(0xffffffffu, m, 1));
    m = fmaxf(m, __shfl_xor_sync(0xffffffffu, m, 2));
    m = fmaxf(m, __shfl_xor_sync(0xffffffffu, m, 4));
    m = fmaxf(m, __shfl_xor_sync(0xffffffffu, m, 8));
    float se = __expf(o - m);
    se += __shfl_xor_sync(0xffffffffu, se, 1);
    se += __shfl_xor_sync(0xffffffffu, se, 2);
    se += __shfl_xor_sync(0xffffffffu, se, 4);
    se += __shfl_xor_sync(0xffffffffu, se, 8);
    float lp = o - m - logf(se);

    if (lane < 16) {
        outO[(size_t)d * 16 + c] = o;
        if (outLP) outLP[(size_t)d * 16 + c] = lp;
    }
}

// ---------------- launch ----------------
extern "C" void kernel_launch(void* const* d_in, const int* in_sizes, int n_in,
                              void* d_out, int out_size) {
    const float* x     = (const float*)d_in[0];
    const int*   ei    = (const int*)d_in[1];
    const float* Wl1   = (const float*)d_in[2];
    const float* bl1   = (const float*)d_in[3];
    const float* Wr1   = (const float*)d_in[4];
    const float* br1   = (const float*)d_in[5];
    const float* att1  = (const float*)d_in[6];
    const float* bias1 = (const float*)d_in[7];
    const float* Wl2   = (const float*)d_in[8];
    const float* bl2   = (const float*)d_in[9];
    const float* Wr2   = (const float*)d_in[10];
    const float* br2   = (const float*)d_in[11];
    const float* att2  = (const float*)d_in[12];
    const float* bias2 = (const float*)d_in[13];

    float* outO  = (float*)d_out;
    float* outLP = (out_size >= 2 * NN * OUTD) ? ((float*)d_out + NN * OUTD) : nullptr;

    k_zero<<<(NN + 255) / 256, 256>>>();
    k_prep<<<512, 256>>>(Wl1, bl1, Wr1, br1, Wl2, bl2, Wr2, br2);
    k_hist<<<(E2 + 255) / 256, 256>>>(ei);
    k_scan1<<<SCAN_BLOCKS, 1024>>>();
    k_scan2<<<1, 32>>>();
    k_scan3<<<SCAN_BLOCKS, 1024>>>();
    k_scatter<<<(E2 + 255) / 256, 256>>>(ei);

    dim3 g1((NN + 127) / 128, 8);
    k_gemm1<<<g1, 256>>>(x);
    k_edge1<<<(NN + 7) / 8, 256>>>(att1, bias1);
    k_gemm2<<<(NN + 7) / 8, 256>>>();
    k_edge2<<<(NN + 7) / 8, 256>>>(att2, bias2, outO, outLP);
}

// round 4
// speedup vs baseline: 1.3691x; 1.2350x over previous
#include <cuda_runtime.h>
#include <cuda_bf16.h>
#include <math.h>
#include <stdint.h>

#define NN 50000
#define EE 400000
#define E2 (EE + NN)
#define OUTD 16
#define MTILES 391  // ceil(50000/128)

// ---------------- scratch (device globals; no allocs allowed) ----------------
__device__ __align__(16) float g_xl1[NN * 256];
__device__ __align__(16) float g_xr1[NN * 256];
__device__ __align__(16) float g_h1[NN * 256];
__device__ __align__(16) float g_e1[E2 * 4];
__device__ __align__(16) float g_xl2[NN * OUTD];
__device__ __align__(16) float g_xr2[NN * OUTD];
__device__ int g_esrc[E2];
__device__ int g_counts[NN];
__device__ int g_fill[NN];
__device__ int g_rowptr[NN + 1];
__device__ int g_bsum[64];
__device__ int g_boff[64];
__device__ __align__(16) float g_bcat1[512];
__device__ __align__(16) float g_Wcat2[256 * 32];
__device__ __align__(16) float g_bcat2[32];
// bf16 hi/lo split operands for tensor-core GEMM1
__device__ __align__(16) __nv_bfloat16 g_Ahi[NN * 256];
__device__ __align__(16) __nv_bfloat16 g_Alo[NN * 256];
__device__ __align__(16) __nv_bfloat16 g_Bhi[512 * 256];
__device__ __align__(16) __nv_bfloat16 g_Blo[512 * 256];

__device__ __forceinline__ float lrelu(float v) { return v > 0.f ? v : 0.2f * v; }

// ---------------- PTX helpers (arch-portable: ldmatrix + mma.sync) ----------------
__device__ __forceinline__ uint32_t smem_u32(const void* p) {
    uint32_t a;
    asm("{ .reg .u64 t; cvta.to.shared.u64 t, %1; cvt.u32.u64 %0, t; }"
        : "=r"(a) : "l"(p));
    return a;
}
__device__ __forceinline__ void cpa16(uint32_t dst, const void* src) {
    asm volatile("cp.async.cg.shared.global [%0], [%1], 16;" ::"r"(dst), "l"(src)
                 : "memory");
}
template <int N>
__device__ __forceinline__ void cpwait() {
    asm volatile("cp.async.wait_group %0;" ::"n"(N) : "memory");
}
__device__ __forceinline__ void ldm4(uint32_t* r, uint32_t addr) {
    asm volatile("ldmatrix.sync.aligned.m8n8.x4.shared.b16 {%0,%1,%2,%3}, [%4];"
                 : "=r"(r[0]), "=r"(r[1]), "=r"(r[2]), "=r"(r[3])
                 : "r"(addr));
}
__device__ __forceinline__ void mma16816(float* c, const uint32_t* a, uint32_t b0,
                                         uint32_t b1) {
    asm volatile(
        "mma.sync.aligned.m16n8k16.row.col.f32.bf16.bf16.f32 "
        "{%0,%1,%2,%3}, {%4,%5,%6,%7}, {%8,%9}, {%0,%1,%2,%3};"
        : "+f"(c[0]), "+f"(c[1]), "+f"(c[2]), "+f"(c[3])
        : "r"(a[0]), "r"(a[1]), "r"(a[2]), "r"(a[3]), "r"(b0), "r"(b1));
}

// ---------------- init ----------------
__global__ void k_zero() {
    int i = blockIdx.x * blockDim.x + threadIdx.x;
    if (i < NN) { g_counts[i] = 0; g_fill[i] = 0; }
}

__global__ void k_prep(const float* __restrict__ bl1, const float* __restrict__ br1,
                       const float* __restrict__ Wl2, const float* __restrict__ bl2,
                       const float* __restrict__ Wr2, const float* __restrict__ br2) {
    for (int i = blockIdx.x * blockDim.x + threadIdx.x; i < 256 * 32;
         i += gridDim.x * blockDim.x) {
        int k2 = i >> 5, n2 = i & 31;
        g_Wcat2[i] = (n2 < 16) ? Wl2[k2 * 16 + n2] : Wr2[k2 * 16 + (n2 - 16)];
        if (i < 512) g_bcat1[i] = (i < 256) ? bl1[i] : br1[i - 256];
        if (i < 32) g_bcat2[i] = (i < 16) ? bl2[i] : br2[i - 16];
    }
}

// ---------------- bf16 hi/lo conversions ----------------
__global__ void k_conv_x(const float* __restrict__ X) {
    int i = blockIdx.x * blockDim.x + threadIdx.x;  // over NN*64 float4s
    if (i >= NN * 64) return;
    float4 v = ((const float4*)X)[i];
    __nv_bfloat16 h0 = __float2bfloat16(v.x);
    __nv_bfloat16 h1 = __float2bfloat16(v.y);
    __nv_bfloat16 h2 = __float2bfloat16(v.z);
    __nv_bfloat16 h3 = __float2bfloat16(v.w);
    __nv_bfloat16 l0 = __float2bfloat16(v.x - __bfloat162float(h0));
    __nv_bfloat16 l1 = __float2bfloat16(v.y - __bfloat162float(h1));
    __nv_bfloat16 l2 = __float2bfloat16(v.z - __bfloat162float(h2));
    __nv_bfloat16 l3 = __float2bfloat16(v.w - __bfloat162float(h3));
    *(__nv_bfloat162*)(g_Ahi + (size_t)i * 4)     = __halves2bfloat162(h0, h1);
    *(__nv_bfloat162*)(g_Ahi + (size_t)i * 4 + 2) = __halves2bfloat162(h2, h3);
    *(__nv_bfloat162*)(g_Alo + (size_t)i * 4)     = __halves2bfloat162(l0, l1);
    *(__nv_bfloat162*)(g_Alo + (size_t)i * 4 + 2) = __halves2bfloat162(l2, l3);
}

// W stored transposed: g_Bhi[n][k] (n-major, K-contiguous) for the MMA B operand
__global__ void k_conv_w(const float* __restrict__ Wl1, const float* __restrict__ Wr1) {
    int i = blockIdx.x * blockDim.x + threadIdx.x;
    if (i >= 512 * 256) return;
    int n = i >> 8, k = i & 255;
    float v = (n < 256) ? Wl1[k * 256 + n] : Wr1[k * 256 + (n - 256)];
    __nv_bfloat16 h = __float2bfloat16(v);
    g_Bhi[n * 256 + k] = h;
    g_Blo[n * 256 + k] = __float2bfloat16(v - __bfloat162float(h));
}

// ---------------- CSR build (dst-sorted) ----------------
__global__ void k_hist(const int* __restrict__ ei) {
    int i = blockIdx.x * blockDim.x + threadIdx.x;
    if (i >= E2) return;
    int dd = (i < EE) ? ei[EE + i] : (i - EE);
    atomicAdd(&g_counts[dd], 1);
}

#define SCAN_BLOCKS 49

__global__ void k_scan1() {
    __shared__ int wsum[32];
    int tid = threadIdx.x;
    int lane = tid & 31, w = tid >> 5;
    int i = blockIdx.x * 1024 + tid;
    int v = (i < NN) ? g_counts[i] : 0;
    int x = v;
#pragma unroll
    for (int st = 1; st < 32; st <<= 1) {
        int y = __shfl_up_sync(0xffffffffu, x, st);
        if (lane >= st) x += y;
    }
    if (lane == 31) wsum[w] = x;
    __syncthreads();
    if (w == 0) {
        int s = wsum[lane];
#pragma unroll
        for (int st = 1; st < 32; st <<= 1) {
            int y = __shfl_up_sync(0xffffffffu, s, st);
            if (lane >= st) s += y;
        }
        wsum[lane] = s;
    }
    __syncthreads();
    int off = (w > 0) ? wsum[w - 1] : 0;
    int incl = x + off;
    if (i < NN) g_rowptr[i] = incl - v;
    if (tid == 1023) g_bsum[blockIdx.x] = incl;
}

__global__ void k_scan2() {
    if (threadIdx.x == 0) {
        int acc = 0;
        for (int b = 0; b < SCAN_BLOCKS; b++) { g_boff[b] = acc; acc += g_bsum[b]; }
        g_rowptr[NN] = acc;
    }
}

__global__ void k_scan3() {
    int i = blockIdx.x * 1024 + threadIdx.x;
    int off = g_boff[blockIdx.x];
    if (i < NN && blockIdx.x > 0) g_rowptr[i] += off;
}

__global__ void k_scatter(const int* __restrict__ ei) {
    int i = blockIdx.x * blockDim.x + threadIdx.x;
    if (i >= E2) return;
    int s  = (i < EE) ? ei[i]      : (i - EE);
    int dd = (i < EE) ? ei[EE + i] : (i - EE);
    int pos = g_rowptr[dd] + atomicAdd(&g_fill[dd], 1);
    g_esrc[pos] = s;
}

// ---------------- GEMM1 (mma.sync bf16 hi/lo): 3 accumulating passes ----------------
// block tile 128x128, warp tile 64x32 (2x4 warp grid), BK=32, 24 chunks.
#define ASTRIDE 40  // bf16 elems per smem row (80B: 16B-aligned, bank-conflict-free)

__global__ void __launch_bounds__(256) k_gemm1_mma() {
    __shared__ __align__(16) __nv_bfloat16 sA[2][128 * ASTRIDE];
    __shared__ __align__(16) __nv_bfloat16 sB[2][128 * ASTRIDE];
    int t = threadIdx.x, lane = t & 31, w = t >> 5;
    int wm = w & 1, wn = w >> 1;
    int m0 = blockIdx.x * 128;
    int n0 = blockIdx.y * 128;

    float acc[4][4][4];
#pragma unroll
    for (int i = 0; i < 4; i++)
#pragma unroll
        for (int j = 0; j < 4; j++)
#pragma unroll
            for (int q = 0; q < 4; q++) acc[i][j][q] = 0.f;

    // chunk c (0..23): pass = c/8 (0:AhiBhi 1:AloBhi 2:AhiBlo), kk = (c%8)*32
    auto issue_load = [&](int c, int s) {
        int pass = c >> 3, kk = (c & 7) * 32;
        const __nv_bfloat16* Asrc = (pass == 1) ? g_Alo : g_Ahi;
        const __nv_bfloat16* Bsrc = (pass == 2) ? g_Blo : g_Bhi;
#pragma unroll
        for (int q = 0; q < 2; q++) {
            int idx = t + q * 256;
            int row = idx >> 2, gi = idx & 3;
            int gm = m0 + row;
            gm = gm < NN ? gm : NN - 1;
            cpa16(smem_u32(&sA[s][row * ASTRIDE + gi * 8]),
                  Asrc + (size_t)gm * 256 + kk + gi * 8);
        }
#pragma unroll
        for (int q = 0; q < 2; q++) {
            int idx = t + q * 256;
            int row = idx >> 2, gi = idx & 3;
            cpa16(smem_u32(&sB[s][row * ASTRIDE + gi * 8]),
                  Bsrc + (size_t)(n0 + row) * 256 + kk + gi * 8);
        }
        asm volatile("cp.async.commit_group;" ::: "memory");
    };

    issue_load(0, 0);
    issue_load(1, 1);

    for (int c = 0; c < 24; c++) {
        int s = c & 1;
        if (c < 23) cpwait<1>(); else cpwait<0>();
        __syncthreads();
#pragma unroll
        for (int ks = 0; ks < 2; ks++) {
            uint32_t a[4][4];
#pragma unroll
            for (int mf = 0; mf < 4; mf++) {
                uint32_t addr = smem_u32(
                    &sA[s][(wm * 64 + mf * 16 + (lane & 15)) * ASTRIDE + ks * 16 +
                           (lane >> 4) * 8]);
                ldm4(a[mf], addr);
            }
            uint32_t b[2][4];
#pragma unroll
            for (int p = 0; p < 2; p++) {
                uint32_t addr = smem_u32(
                    &sB[s][(wn * 32 + p * 16 + (lane & 7) + ((lane >> 4) & 1) * 8) *
                               ASTRIDE +
                           ks * 16 + ((lane >> 3) & 1) * 8]);
                ldm4(b[p], addr);
            }
#pragma unroll
            for (int mf = 0; mf < 4; mf++)
#pragma unroll
                for (int nf = 0; nf < 4; nf++) {
                    int p = nf >> 1, hi = (nf & 1) * 2;
                    mma16816(acc[mf][nf], a[mf], b[p][hi], b[p][hi + 1]);
                }
        }
        __syncthreads();
        if (c + 2 < 24) issue_load(c + 2, s);
    }

    // epilogue: add bias, write to g_xl1/g_xr1
#pragma unroll
    for (int mf = 0; mf < 4; mf++) {
        int row0 = m0 + wm * 64 + mf * 16 + (lane >> 2);
#pragma unroll
        for (int nf = 0; nf < 4; nf++) {
            int col = n0 + wn * 32 + nf * 8 + (lane & 3) * 2;
            float b0 = g_bcat1[col], b1 = g_bcat1[col + 1];
            float* base = (col < 256) ? g_xl1 : g_xr1;
            int cc = (col < 256) ? col : col - 256;
            if (row0 < NN) {
                float2 v = make_float2(acc[mf][nf][0] + b0, acc[mf][nf][1] + b1);
                *(float2*)(base + (size_t)row0 * 256 + cc) = v;
            }
            if (row0 + 8 < NN) {
                float2 v = make_float2(acc[mf][nf][2] + b0, acc[mf][nf][3] + b1);
                *(float2*)(base + (size_t)(row0 + 8) * 256 + cc) = v;
            }
        }
    }
}

// ---------------- layer-1 edge phase: warp per dst node ----------------
__global__ void k_edge1(const float* __restrict__ att1, const float* __restrict__ bias1) {
    int gw = (blockIdx.x * blockDim.x + threadIdx.x) >> 5;
    int lane = threadIdx.x & 31;
    if (gw >= NN) return;
    int d = gw;
    int cb = lane * 8;
    const float4* xrp = (const float4*)(g_xr1 + (size_t)d * 256 + cb);
    float4 xr0 = xrp[0], xr1v = xrp[1];
    const float4* ap = (const float4*)(att1 + cb);
    float4 at0 = ap[0], at1 = ap[1];
    int p0 = g_rowptr[d], p1 = g_rowptr[d + 1];
    int head = lane >> 3;

    float maxe = -INFINITY;
    for (int p = p0; p < p1; p++) {
        int s = g_esrc[p];
        const float4* xs = (const float4*)(g_xl1 + (size_t)s * 256 + cb);
        float4 a0 = xs[0], a1 = xs[1];
        float pa = lrelu(a0.x + xr0.x) * at0.x + lrelu(a0.y + xr0.y) * at0.y +
                   lrelu(a0.z + xr0.z) * at0.z + lrelu(a0.w + xr0.w) * at0.w +
                   lrelu(a1.x + xr1v.x) * at1.x + lrelu(a1.y + xr1v.y) * at1.y +
                   lrelu(a1.z + xr1v.z) * at1.z + lrelu(a1.w + xr1v.w) * at1.w;
        pa += __shfl_xor_sync(0xffffffffu, pa, 1);
        pa += __shfl_xor_sync(0xffffffffu, pa, 2);
        pa += __shfl_xor_sync(0xffffffffu, pa, 4);
        if ((lane & 7) == 0) g_e1[(size_t)p * 4 + head] = pa;
        maxe = fmaxf(maxe, pa);
    }
    __threadfence_block();
    __syncwarp();

    float4 acc0 = make_float4(0.f, 0.f, 0.f, 0.f), acc1 = acc0;
    float denom = 0.f;
    for (int p = p0; p < p1; p++) {
        int s = g_esrc[p];
        float ee = __expf(g_e1[(size_t)p * 4 + head] - maxe);
        denom += ee;
        const float4* xs = (const float4*)(g_xl1 + (size_t)s * 256 + cb);
        float4 a0 = xs[0], a1 = xs[1];
        acc0.x += ee * a0.x; acc0.y += ee * a0.y; acc0.z += ee * a0.z; acc0.w += ee * a0.w;
        acc1.x += ee * a1.x; acc1.y += ee * a1.y; acc1.z += ee * a1.z; acc1.w += ee * a1.w;
    }
    float inv = 1.f / (denom + 1e-16f);
    const float4* bp = (const float4*)(bias1 + cb);
    float4 b0 = bp[0], b1 = bp[1];
    float4 o0, o1;
    o0.x = tanhf(acc0.x * inv + b0.x); o0.y = tanhf(acc0.y * inv + b0.y);
    o0.z = tanhf(acc0.z * inv + b0.z); o0.w = tanhf(acc0.w * inv + b0.w);
    o1.x = tanhf(acc1.x * inv + b1.x); o1.y = tanhf(acc1.y * inv + b1.y);
    o1.z = tanhf(acc1.z * inv + b1.z); o1.w = tanhf(acc1.w * inv + b1.w);
    float4* hp = (float4*)(g_h1 + (size_t)d * 256 + cb);
    hp[0] = o0; hp[1] = o1;
}

// ---------------- GEMM2 ----------------
__global__ void k_gemm2() {
    __shared__ float Ws[256 * 32];
    int t = threadIdx.x;
    for (int i = t; i < 256 * 32; i += 256) Ws[i] = g_Wcat2[i];
    __syncthreads();
    int warp = t >> 5, lane = t & 31;
    int row = blockIdx.x * 8 + warp;
    if (row >= NN) return;
    float acc = 0.f;
    const float* hrow = g_h1 + (size_t)row * 256;
    for (int k0 = 0; k0 < 256; k0 += 32) {
        float hv = hrow[k0 + lane];
#pragma unroll
        for (int j = 0; j < 32; j++) {
            float hb = __shfl_sync(0xffffffffu, hv, j);
            acc += hb * Ws[(k0 + j) * 32 + lane];
        }
    }
    float v = acc + g_bcat2[lane];
    if (lane < 16) g_xl2[(size_t)row * 16 + lane] = v;
    else           g_xr2[(size_t)row * 16 + (lane - 16)] = v;
}

// ---------------- layer-2 edge phase + log_softmax ----------------
__global__ void k_edge2(const float* __restrict__ att2, const float* __restrict__ bias2,
                        float* __restrict__ outO, float* __restrict__ outLP) {
    int gw = (blockIdx.x * blockDim.x + threadIdx.x) >> 5;
    int lane = threadIdx.x & 31;
    if (gw >= NN) return;
    int d = gw;
    int c = lane & 15;
    float xrv = g_xr2[(size_t)d * 16 + c];
    float av = att2[c];
    int p0 = g_rowptr[d], p1 = g_rowptr[d + 1];

    float maxe = -INFINITY;
    for (int p = p0; p < p1; p++) {
        int s = g_esrc[p];
        float v = g_xl2[(size_t)s * 16 + c] + xrv;
        v = v > 0.f ? v : 0.2f * v;
        float pa = v * av;
        pa += __shfl_xor_sync(0xffffffffu, pa, 1);
        pa += __shfl_xor_sync(0xffffffffu, pa, 2);
        pa += __shfl_xor_sync(0xffffffffu, pa, 4);
        pa += __shfl_xor_sync(0xffffffffu, pa, 8);
        if (lane == 0) g_e1[p] = pa;
        maxe = fmaxf(maxe, pa);
    }
    __threadfence_block();
    __syncwarp();

    float acc = 0.f, denom = 0.f;
    for (int p = p0; p < p1; p++) {
        int s = g_esrc[p];
        float ee = __expf(g_e1[p] - maxe);
        denom += ee;
        acc += ee * g_xl2[(size_t)s * 16 + c];
    }
    float o = acc / (denom + 1e-16f) + bias2[c];

    float m = o;
    m = fmaxf(m, __shfl_xor_sync(0xffffffffu, m, 1));
    m = fmaxf(m, __shfl_xor_sync(0xffffffffu, m, 2));
    m = fmaxf(m, __shfl_xor_sync(0xffffffffu, m, 4));
    m = fmaxf(m, __shfl_xor_sync(0xffffffffu, m, 8));
    float se = __expf(o - m);
    se += __shfl_xor_sync(0xffffffffu, se, 1);
    se += __shfl_xor_sync(0xffffffffu, se, 2);
    se += __shfl_xor_sync(0xffffffffu, se, 4);
    se += __shfl_xor_sync(0xffffffffu, se, 8);
    float lp = o - m - logf(se);

    if (lane < 16) {
        outO[(size_t)d * 16 + c] = o;
        if (outLP) outLP[(size_t)d * 16 + c] = lp;
    }
}

// ---------------- launch ----------------
extern "C" void kernel_launch(void* const* d_in, const int* in_sizes, int n_in,
                              void* d_out, int out_size) {
    const float* x     = (const float*)d_in[0];
    const int*   ei    = (const int*)d_in[1];
    const float* Wl1   = (const float*)d_in[2];
    const float* bl1   = (const float*)d_in[3];
    const float* Wr1   = (const float*)d_in[4];
    const float* br1   = (const float*)d_in[5];
    const float* att1  = (const float*)d_in[6];
    const float* bias1 = (const float*)d_in[7];
    const float* Wl2   = (const float*)d_in[8];
    const float* bl2   = (const float*)d_in[9];
    const float* Wr2   = (const float*)d_in[10];
    const float* br2   = (const float*)d_in[11];
    const float* att2  = (const float*)d_in[12];
    const float* bias2 = (const float*)d_in[13];

    float* outO  = (float*)d_out;
    float* outLP = (out_size >= 2 * NN * OUTD) ? ((float*)d_out + NN * OUTD) : nullptr;

    k_zero<<<(NN + 255) / 256, 256>>>();
    k_prep<<<32, 256>>>(bl1, br1, Wl2, bl2, Wr2, br2);
    k_conv_x<<<(NN * 64 + 255) / 256, 256>>>(x);
    k_conv_w<<<512, 256>>>(Wl1, Wr1);
    k_hist<<<(E2 + 255) / 256, 256>>>(ei);
    k_scan1<<<SCAN_BLOCKS, 1024>>>();
    k_scan2<<<1, 32>>>();
    k_scan3<<<SCAN_BLOCKS, 1024>>>();
    k_scatter<<<(E2 + 255) / 256, 256>>>(ei);

    dim3 g1(MTILES, 4);
    k_gemm1_mma<<<g1, 256>>>();
    k_edge1<<<(NN + 7) / 8, 256>>>(att1, bias1);
    k_gemm2<<<(NN + 7) / 8, 256>>>();
    k_edge2<<<(NN + 7) / 8, 256>>>(att2, bias2, outO, outLP);
}

// round 5
// speedup vs baseline: 1.4749x; 1.0772x over previous
#include <cuda_runtime.h>
#include <cuda_bf16.h>
#include <math.h>
#include <stdint.h>

#define NN 50000
#define EE 400000
#define E2 (EE + NN)
#define OUTD 16
#define MTILES 391  // ceil(50000/128)

// ---------------- scratch (device globals; no allocs allowed) ----------------
__device__ __align__(16) float g_xl1[NN * 256];
__device__ __align__(16) float g_xr1[NN * 256];
__device__ __align__(16) float g_h1[NN * 256];
__device__ __align__(16) float g_xl2[NN * OUTD];
__device__ __align__(16) float g_xr2[NN * OUTD];
__device__ int g_esrc[E2];
__device__ int g_counts[NN];
__device__ int g_fill[NN];
__device__ int g_rowptr[NN + 1];
__device__ int g_bsum[64];
__device__ int g_boff[64];
__device__ __align__(16) float g_bcat1[512];
__device__ __align__(16) float g_Wcat2[256 * 32];
__device__ __align__(16) float g_bcat2[32];
// bf16 hi/lo split operands for tensor-core GEMM1
__device__ __align__(16) __nv_bfloat16 g_Ahi[NN * 256];
__device__ __align__(16) __nv_bfloat16 g_Alo[NN * 256];
__device__ __align__(16) __nv_bfloat16 g_Bhi[512 * 256];
__device__ __align__(16) __nv_bfloat16 g_Blo[512 * 256];

__device__ __forceinline__ float lrelu(float v) { return v > 0.f ? v : 0.2f * v; }

// ---------------- PTX helpers (arch-portable: ldmatrix + mma.sync) ----------------
__device__ __forceinline__ uint32_t smem_u32(const void* p) {
    uint32_t a;
    asm("{ .reg .u64 t; cvta.to.shared.u64 t, %1; cvt.u32.u64 %0, t; }"
        : "=r"(a) : "l"(p));
    return a;
}
__device__ __forceinline__ void cpa16(uint32_t dst, const void* src) {
    asm volatile("cp.async.cg.shared.global [%0], [%1], 16;" ::"r"(dst), "l"(src)
                 : "memory");
}
template <int N>
__device__ __forceinline__ void cpwait() {
    asm volatile("cp.async.wait_group %0;" ::"n"(N) : "memory");
}
__device__ __forceinline__ void ldm4(uint32_t* r, uint32_t addr) {
    asm volatile("ldmatrix.sync.aligned.m8n8.x4.shared.b16 {%0,%1,%2,%3}, [%4];"
                 : "=r"(r[0]), "=r"(r[1]), "=r"(r[2]), "=r"(r[3])
                 : "r"(addr));
}
__device__ __forceinline__ void mma16816(float* c, const uint32_t* a, uint32_t b0,
                                         uint32_t b1) {
    asm volatile(
        "mma.sync.aligned.m16n8k16.row.col.f32.bf16.bf16.f32 "
        "{%0,%1,%2,%3}, {%4,%5,%6,%7}, {%8,%9}, {%0,%1,%2,%3};"
        : "+f"(c[0]), "+f"(c[1]), "+f"(c[2]), "+f"(c[3])
        : "r"(a[0]), "r"(a[1]), "r"(a[2]), "r"(a[3]), "r"(b0), "r"(b1));
}

// ---------------- init ----------------
__global__ void k_zero() {
    int i = blockIdx.x * blockDim.x + threadIdx.x;
    if (i < NN) { g_counts[i] = 0; g_fill[i] = 0; }
}

__global__ void k_prep(const float* __restrict__ bl1, const float* __restrict__ br1,
                       const float* __restrict__ Wl2, const float* __restrict__ bl2,
                       const float* __restrict__ Wr2, const float* __restrict__ br2) {
    for (int i = blockIdx.x * blockDim.x + threadIdx.x; i < 256 * 32;
         i += gridDim.x * blockDim.x) {
        int k2 = i >> 5, n2 = i & 31;
        g_Wcat2[i] = (n2 < 16) ? Wl2[k2 * 16 + n2] : Wr2[k2 * 16 + (n2 - 16)];
        if (i < 512) g_bcat1[i] = (i < 256) ? bl1[i] : br1[i - 256];
        if (i < 32) g_bcat2[i] = (i < 16) ? bl2[i] : br2[i - 16];
    }
}

// ---------------- bf16 hi/lo conversions ----------------
__global__ void k_conv_x(const float* __restrict__ X) {
    int i = blockIdx.x * blockDim.x + threadIdx.x;  // over NN*64 float4s
    if (i >= NN * 64) return;
    float4 v = ((const float4*)X)[i];
    __nv_bfloat16 h0 = __float2bfloat16(v.x);
    __nv_bfloat16 h1 = __float2bfloat16(v.y);
    __nv_bfloat16 h2 = __float2bfloat16(v.z);
    __nv_bfloat16 h3 = __float2bfloat16(v.w);
    __nv_bfloat16 l0 = __float2bfloat16(v.x - __bfloat162float(h0));
    __nv_bfloat16 l1 = __float2bfloat16(v.y - __bfloat162float(h1));
    __nv_bfloat16 l2 = __float2bfloat16(v.z - __bfloat162float(h2));
    __nv_bfloat16 l3 = __float2bfloat16(v.w - __bfloat162float(h3));
    *(__nv_bfloat162*)(g_Ahi + (size_t)i * 4)     = __halves2bfloat162(h0, h1);
    *(__nv_bfloat162*)(g_Ahi + (size_t)i * 4 + 2) = __halves2bfloat162(h2, h3);
    *(__nv_bfloat162*)(g_Alo + (size_t)i * 4)     = __halves2bfloat162(l0, l1);
    *(__nv_bfloat162*)(g_Alo + (size_t)i * 4 + 2) = __halves2bfloat162(l2, l3);
}

// W stored transposed: g_Bhi[n][k] (n-major, K-contiguous) for the MMA B operand
__global__ void k_conv_w(const float* __restrict__ Wl1, const float* __restrict__ Wr1) {
    int i = blockIdx.x * blockDim.x + threadIdx.x;
    if (i >= 512 * 256) return;
    int n = i >> 8, k = i & 255;
    float v = (n < 256) ? Wl1[k * 256 + n] : Wr1[k * 256 + (n - 256)];
    __nv_bfloat16 h = __float2bfloat16(v);
    g_Bhi[n * 256 + k] = h;
    g_Blo[n * 256 + k] = __float2bfloat16(v - __bfloat162float(h));
}

// ---------------- CSR build (dst-sorted) ----------------
__global__ void k_hist(const int* __restrict__ ei) {
    int i = blockIdx.x * blockDim.x + threadIdx.x;
    if (i >= E2) return;
    int dd = (i < EE) ? ei[EE + i] : (i - EE);
    atomicAdd(&g_counts[dd], 1);
}

#define SCAN_BLOCKS 49

__global__ void k_scan1() {
    __shared__ int wsum[32];
    int tid = threadIdx.x;
    int lane = tid & 31, w = tid >> 5;
    int i = blockIdx.x * 1024 + tid;
    int v = (i < NN) ? g_counts[i] : 0;
    int x = v;
#pragma unroll
    for (int st = 1; st < 32; st <<= 1) {
        int y = __shfl_up_sync(0xffffffffu, x, st);
        if (lane >= st) x += y;
    }
    if (lane == 31) wsum[w] = x;
    __syncthreads();
    if (w == 0) {
        int s = wsum[lane];
#pragma unroll
        for (int st = 1; st < 32; st <<= 1) {
            int y = __shfl_up_sync(0xffffffffu, s, st);
            if (lane >= st) s += y;
        }
        wsum[lane] = s;
    }
    __syncthreads();
    int off = (w > 0) ? wsum[w - 1] : 0;
    int incl = x + off;
    if (i < NN) g_rowptr[i] = incl - v;
    if (tid == 1023) g_bsum[blockIdx.x] = incl;
}

__global__ void k_scan2() {
    if (threadIdx.x == 0) {
        int acc = 0;
        for (int b = 0; b < SCAN_BLOCKS; b++) { g_boff[b] = acc; acc += g_bsum[b]; }
        g_rowptr[NN] = acc;
    }
}

__global__ void k_scan3() {
    int i = blockIdx.x * 1024 + threadIdx.x;
    int off = g_boff[blockIdx.x];
    if (i < NN && blockIdx.x > 0) g_rowptr[i] += off;
}

__global__ void k_scatter(const int* __restrict__ ei) {
    int i = blockIdx.x * blockDim.x + threadIdx.x;
    if (i >= E2) return;
    int s  = (i < EE) ? ei[i]      : (i - EE);
    int dd = (i < EE) ? ei[EE + i] : (i - EE);
    int pos = g_rowptr[dd] + atomicAdd(&g_fill[dd], 1);
    g_esrc[pos] = s;
}

// ---------------- GEMM1 (mma.sync bf16 hi/lo): 3 accumulating passes ----------------
// block tile 128x128, warp tile 64x32 (2x4 warp grid), BK=32, 24 chunks.
#define ASTRIDE 40  // bf16 elems per smem row (80B: 16B-aligned, bank-conflict-free)

__global__ void __launch_bounds__(256) k_gemm1_mma() {
    __shared__ __align__(16) __nv_bfloat16 sA[2][128 * ASTRIDE];
    __shared__ __align__(16) __nv_bfloat16 sB[2][128 * ASTRIDE];
    int t = threadIdx.x, lane = t & 31, w = t >> 5;
    int wm = w & 1, wn = w >> 1;
    int m0 = blockIdx.x * 128;
    int n0 = blockIdx.y * 128;

    float acc[4][4][4];
#pragma unroll
    for (int i = 0; i < 4; i++)
#pragma unroll
        for (int j = 0; j < 4; j++)
#pragma unroll
            for (int q = 0; q < 4; q++) acc[i][j][q] = 0.f;

    // chunk c (0..23): pass = c/8 (0:AhiBhi 1:AloBhi 2:AhiBlo), kk = (c%8)*32
    auto issue_load = [&](int c, int s) {
        int pass = c >> 3, kk = (c & 7) * 32;
        const __nv_bfloat16* Asrc = (pass == 1) ? g_Alo : g_Ahi;
        const __nv_bfloat16* Bsrc = (pass == 2) ? g_Blo : g_Bhi;
#pragma unroll
        for (int q = 0; q < 2; q++) {
            int idx = t + q * 256;
            int row = idx >> 2, gi = idx & 3;
            int gm = m0 + row;
            gm = gm < NN ? gm : NN - 1;
            cpa16(smem_u32(&sA[s][row * ASTRIDE + gi * 8]),
                  Asrc + (size_t)gm * 256 + kk + gi * 8);
        }
#pragma unroll
        for (int q = 0; q < 2; q++) {
            int idx = t + q * 256;
            int row = idx >> 2, gi = idx & 3;
            cpa16(smem_u32(&sB[s][row * ASTRIDE + gi * 8]),
                  Bsrc + (size_t)(n0 + row) * 256 + kk + gi * 8);
        }
        asm volatile("cp.async.commit_group;" ::: "memory");
    };

    issue_load(0, 0);
    issue_load(1, 1);

    for (int c = 0; c < 24; c++) {
        int s = c & 1;
        if (c < 23) cpwait<1>(); else cpwait<0>();
        __syncthreads();
#pragma unroll
        for (int ks = 0; ks < 2; ks++) {
            uint32_t a[4][4];
#pragma unroll
            for (int mf = 0; mf < 4; mf++) {
                uint32_t addr = smem_u32(
                    &sA[s][(wm * 64 + mf * 16 + (lane & 15)) * ASTRIDE + ks * 16 +
                           (lane >> 4) * 8]);
                ldm4(a[mf], addr);
            }
            uint32_t b[2][4];
#pragma unroll
            for (int p = 0; p < 2; p++) {
                uint32_t addr = smem_u32(
                    &sB[s][(wn * 32 + p * 16 + (lane & 7) + ((lane >> 4) & 1) * 8) *
                               ASTRIDE +
                           ks * 16 + ((lane >> 3) & 1) * 8]);
                ldm4(b[p], addr);
            }
#pragma unroll
            for (int mf = 0; mf < 4; mf++)
#pragma unroll
                for (int nf = 0; nf < 4; nf++) {
                    int p = nf >> 1, hi = (nf & 1) * 2;
                    mma16816(acc[mf][nf], a[mf], b[p][hi], b[p][hi + 1]);
                }
        }
        __syncthreads();
        if (c + 2 < 24) issue_load(c + 2, s);
    }

    // epilogue: add bias, write to g_xl1/g_xr1
#pragma unroll
    for (int mf = 0; mf < 4; mf++) {
        int row0 = m0 + wm * 64 + mf * 16 + (lane >> 2);
#pragma unroll
        for (int nf = 0; nf < 4; nf++) {
            int col = n0 + wn * 32 + nf * 8 + (lane & 3) * 2;
            float b0 = g_bcat1[col], b1 = g_bcat1[col + 1];
            float* base = (col < 256) ? g_xl1 : g_xr1;
            int cc = (col < 256) ? col : col - 256;
            if (row0 < NN) {
                float2 v = make_float2(acc[mf][nf][0] + b0, acc[mf][nf][1] + b1);
                *(float2*)(base + (size_t)row0 * 256 + cc) = v;
            }
            if (row0 + 8 < NN) {
                float2 v = make_float2(acc[mf][nf][2] + b0, acc[mf][nf][3] + b1);
                *(float2*)(base + (size_t)(row0 + 8) * 256 + cc) = v;
            }
        }
    }
}

// ---------------- layer-1 edge phase: warp per dst node, online softmax ----------------
__global__ void k_edge1(const float* __restrict__ att1, const float* __restrict__ bias1) {
    int gw = (blockIdx.x * blockDim.x + threadIdx.x) >> 5;
    int lane = threadIdx.x & 31;
    if (gw >= NN) return;
    int d = gw;
    int cb = lane * 8;  // 8 channels per lane; head = lane>>3
    const float4* xrp = (const float4*)(g_xr1 + (size_t)d * 256 + cb);
    float4 xr0 = xrp[0], xr1v = xrp[1];
    const float4* ap = (const float4*)(att1 + cb);
    float4 at0 = ap[0], at1 = ap[1];
    int p0 = g_rowptr[d], p1 = g_rowptr[d + 1];

    float m = -INFINITY, denom = 0.f;
    float4 acc0 = make_float4(0.f, 0.f, 0.f, 0.f), acc1 = acc0;

    for (int p = p0; p < p1; p++) {
        int s = g_esrc[p];
        const float4* xs = (const float4*)(g_xl1 + (size_t)s * 256 + cb);
        float4 a0 = xs[0], a1 = xs[1];
        float pa = lrelu(a0.x + xr0.x) * at0.x + lrelu(a0.y + xr0.y) * at0.y +
                   lrelu(a0.z + xr0.z) * at0.z + lrelu(a0.w + xr0.w) * at0.w +
                   lrelu(a1.x + xr1v.x) * at1.x + lrelu(a1.y + xr1v.y) * at1.y +
                   lrelu(a1.z + xr1v.z) * at1.z + lrelu(a1.w + xr1v.w) * at1.w;
        pa += __shfl_xor_sync(0xffffffffu, pa, 1);
        pa += __shfl_xor_sync(0xffffffffu, pa, 2);
        pa += __shfl_xor_sync(0xffffffffu, pa, 4);
        // online softmax update (per-head; all 8 lanes of a head agree on pa/m)
        if (pa > m) {
            float sc = __expf(m - pa);  // first time: exp(-inf)=0
            denom *= sc;
            acc0.x *= sc; acc0.y *= sc; acc0.z *= sc; acc0.w *= sc;
            acc1.x *= sc; acc1.y *= sc; acc1.z *= sc; acc1.w *= sc;
            m = pa;
        }
        float ee = __expf(pa - m);
        denom += ee;
        acc0.x += ee * a0.x; acc0.y += ee * a0.y; acc0.z += ee * a0.z; acc0.w += ee * a0.w;
        acc1.x += ee * a1.x; acc1.y += ee * a1.y; acc1.z += ee * a1.z; acc1.w += ee * a1.w;
    }
    float inv = 1.f / (denom + 1e-16f);
    const float4* bp = (const float4*)(bias1 + cb);
    float4 b0 = bp[0], b1 = bp[1];
    float4 o0, o1;
    o0.x = tanhf(acc0.x * inv + b0.x); o0.y = tanhf(acc0.y * inv + b0.y);
    o0.z = tanhf(acc0.z * inv + b0.z); o0.w = tanhf(acc0.w * inv + b0.w);
    o1.x = tanhf(acc1.x * inv + b1.x); o1.y = tanhf(acc1.y * inv + b1.y);
    o1.z = tanhf(acc1.z * inv + b1.z); o1.w = tanhf(acc1.w * inv + b1.w);
    float4* hp = (float4*)(g_h1 + (size_t)d * 256 + cb);
    hp[0] = o0; hp[1] = o1;
}

// ---------------- GEMM2 ----------------
__global__ void k_gemm2() {
    __shared__ float Ws[256 * 32];
    int t = threadIdx.x;
    for (int i = t; i < 256 * 32; i += 256) Ws[i] = g_Wcat2[i];
    __syncthreads();
    int warp = t >> 5, lane = t & 31;
    int row = blockIdx.x * 8 + warp;
    if (row >= NN) return;
    float acc = 0.f;
    const float* hrow = g_h1 + (size_t)row * 256;
    for (int k0 = 0; k0 < 256; k0 += 32) {
        float hv = hrow[k0 + lane];
#pragma unroll
        for (int j = 0; j < 32; j++) {
            float hb = __shfl_sync(0xffffffffu, hv, j);
            acc += hb * Ws[(k0 + j) * 32 + lane];
        }
    }
    float v = acc + g_bcat2[lane];
    if (lane < 16) g_xl2[(size_t)row * 16 + lane] = v;
    else           g_xr2[(size_t)row * 16 + (lane - 16)] = v;
}

// ---------------- layer-2 edge phase + log_softmax: online softmax ----------------
__global__ void k_edge2(const float* __restrict__ att2, const float* __restrict__ bias2,
                        float* __restrict__ outO, float* __restrict__ outLP) {
    int gw = (blockIdx.x * blockDim.x + threadIdx.x) >> 5;
    int lane = threadIdx.x & 31;
    if (gw >= NN) return;
    int d = gw;
    int c = lane & 15;  // both 16-lane halves mirror the same work
    float xrv = g_xr2[(size_t)d * 16 + c];
    float av = att2[c];
    int p0 = g_rowptr[d], p1 = g_rowptr[d + 1];

    float m = -INFINITY, denom = 0.f, acc = 0.f;
    for (int p = p0; p < p1; p++) {
        int s = g_esrc[p];
        float xv = g_xl2[(size_t)s * 16 + c];
        float v = xv + xrv;
        v = v > 0.f ? v : 0.2f * v;
        float pa = v * av;
        pa += __shfl_xor_sync(0xffffffffu, pa, 1);
        pa += __shfl_xor_sync(0xffffffffu, pa, 2);
        pa += __shfl_xor_sync(0xffffffffu, pa, 4);
        pa += __shfl_xor_sync(0xffffffffu, pa, 8);
        if (pa > m) {
            float sc = __expf(m - pa);
            denom *= sc;
            acc *= sc;
            m = pa;
        }
        float ee = __expf(pa - m);
        denom += ee;
        acc += ee * xv;
    }
    float o = acc / (denom + 1e-16f) + bias2[c];

    // log_softmax over the 16 channels (within each 16-lane half)
    float mm = o;
    mm = fmaxf(mm, __shfl_xor_sync(0xffffffffu, mm, 1));
    mm = fmaxf(mm, __shfl_xor_sync(0xffffffffu, mm, 2));
    mm = fmaxf(mm, __shfl_xor_sync(0xffffffffu, mm, 4));
    mm = fmaxf(mm, __shfl_xor_sync(0xffffffffu, mm, 8));
    float se = __expf(o - mm);
    se += __shfl_xor_sync(0xffffffffu, se, 1);
    se += __shfl_xor_sync(0xffffffffu, se, 2);
    se += __shfl_xor_sync(0xffffffffu, se, 4);
    se += __shfl_xor_sync(0xffffffffu, se, 8);
    float lp = o - mm - logf(se);

    if (lane < 16) {
        outO[(size_t)d * 16 + c] = o;
        if (outLP) outLP[(size_t)d * 16 + c] = lp;
    }
}

// ---------------- launch ----------------
extern "C" void kernel_launch(void* const* d_in, const int* in_sizes, int n_in,
                              void* d_out, int out_size) {
    const float* x     = (const float*)d_in[0];
    const int*   ei    = (const int*)d_in[1];
    const float* Wl1   = (const float*)d_in[2];
    const float* bl1   = (const float*)d_in[3];
    const float* Wr1   = (const float*)d_in[4];
    const float* br1   = (const float*)d_in[5];
    const float* att1  = (const float*)d_in[6];
    const float* bias1 = (const float*)d_in[7];
    const float* Wl2   = (const float*)d_in[8];
    const float* bl2   = (const float*)d_in[9];
    const float* Wr2   = (const float*)d_in[10];
    const float* br2   = (const float*)d_in[11];
    const float* att2  = (const float*)d_in[12];
    const float* bias2 = (const float*)d_in[13];

    float* outO  = (float*)d_out;
    float* outLP = (out_size >= 2 * NN * OUTD) ? ((float*)d_out + NN * OUTD) : nullptr;

    k_zero<<<(NN + 255) / 256, 256>>>();
    k_prep<<<32, 256>>>(bl1, br1, Wl2, bl2, Wr2, br2);
    k_conv_x<<<(NN * 64 + 255) / 256, 256>>>(x);
    k_conv_w<<<512, 256>>>(Wl1, Wr1);
    k_hist<<<(E2 + 255) / 256, 256>>>(ei);
    k_scan1<<<SCAN_BLOCKS, 1024>>>();
    k_scan2<<<1, 32>>>();
    k_scan3<<<SCAN_BLOCKS, 1024>>>();
    k_scatter<<<(E2 + 255) / 256, 256>>>(ei);

    dim3 g1(MTILES, 4);
    k_gemm1_mma<<<g1, 256>>>();
    k_edge1<<<(NN + 7) / 8, 256>>>(att1, bias1);
    k_gemm2<<<(NN + 7) / 8, 256>>>();
    k_edge2<<<(NN + 7) / 8, 256>>>(att2, bias2, outO, outLP);
}

// round 6
// speedup vs baseline: 1.4771x; 1.0015x over previous
#include <cuda_runtime.h>
#include <cuda_bf16.h>
#include <math.h>
#include <stdint.h>

#define NN 50000
#define EE 400000
#define E2 (EE + NN)
#define OUTD 16
#define MTILES 391  // ceil(50000/128)

// ---------------- scratch (device globals; no allocs allowed) ----------------
__device__ __align__(16) float g_xl1[NN * 256];
__device__ __align__(16) float g_xr1[NN * 256];
__device__ __align__(16) float g_h1[NN * 256];
__device__ __align__(16) float g_xl2[NN * OUTD];
__device__ __align__(16) float g_xr2[NN * OUTD];
__device__ int g_esrc[E2];
__device__ int g_counts[NN];
__device__ int g_fill[NN];
__device__ int g_rowptr[NN + 1];
__device__ int g_bsum[64];
__device__ int g_boff[64];
__device__ __align__(16) float g_bcat1[512];
__device__ __align__(16) float g_Wcat2[256 * 32];
__device__ __align__(16) float g_bcat2[32];
// bf16 hi/lo split operands for tensor-core GEMM1
__device__ __align__(16) __nv_bfloat16 g_Ahi[NN * 256];
__device__ __align__(16) __nv_bfloat16 g_Alo[NN * 256];
__device__ __align__(16) __nv_bfloat16 g_Bhi[512 * 256];
__device__ __align__(16) __nv_bfloat16 g_Blo[512 * 256];

__device__ __forceinline__ float lrelu(float v) { return v > 0.f ? v : 0.2f * v; }

// ---------------- PTX helpers (arch-portable: ldmatrix + mma.sync) ----------------
__device__ __forceinline__ uint32_t smem_u32(const void* p) {
    uint32_t a;
    asm("{ .reg .u64 t; cvta.to.shared.u64 t, %1; cvt.u32.u64 %0, t; }"
        : "=r"(a) : "l"(p));
    return a;
}
__device__ __forceinline__ void cpa16(uint32_t dst, const void* src) {
    asm volatile("cp.async.cg.shared.global [%0], [%1], 16;" ::"r"(dst), "l"(src)
                 : "memory");
}
template <int N>
__device__ __forceinline__ void cpwait() {
    asm volatile("cp.async.wait_group %0;" ::"n"(N) : "memory");
}
__device__ __forceinline__ void ldm4(uint32_t* r, uint32_t addr) {
    asm volatile("ldmatrix.sync.aligned.m8n8.x4.shared.b16 {%0,%1,%2,%3}, [%4];"
                 : "=r"(r[0]), "=r"(r[1]), "=r"(r[2]), "=r"(r[3])
                 : "r"(addr));
}
__device__ __forceinline__ void mma16816(float* c, const uint32_t* a, uint32_t b0,
                                         uint32_t b1) {
    asm volatile(
        "mma.sync.aligned.m16n8k16.row.col.f32.bf16.bf16.f32 "
        "{%0,%1,%2,%3}, {%4,%5,%6,%7}, {%8,%9}, {%0,%1,%2,%3};"
        : "+f"(c[0]), "+f"(c[1]), "+f"(c[2]), "+f"(c[3])
        : "r"(a[0]), "r"(a[1]), "r"(a[2]), "r"(a[3]), "r"(b0), "r"(b1));
}

// ---------------- init ----------------
__global__ void k_zero() {
    int i = blockIdx.x * blockDim.x + threadIdx.x;
    if (i < NN) { g_counts[i] = 0; g_fill[i] = 0; }
}

__global__ void k_prep(const float* __restrict__ bl1, const float* __restrict__ br1,
                       const float* __restrict__ Wl2, const float* __restrict__ bl2,
                       const float* __restrict__ Wr2, const float* __restrict__ br2) {
    for (int i = blockIdx.x * blockDim.x + threadIdx.x; i < 256 * 32;
         i += gridDim.x * blockDim.x) {
        int k2 = i >> 5, n2 = i & 31;
        g_Wcat2[i] = (n2 < 16) ? Wl2[k2 * 16 + n2] : Wr2[k2 * 16 + (n2 - 16)];
        if (i < 512) g_bcat1[i] = (i < 256) ? bl1[i] : br1[i - 256];
        if (i < 32) g_bcat2[i] = (i < 16) ? bl2[i] : br2[i - 16];
    }
}

// ---------------- bf16 hi/lo conversions ----------------
__global__ void k_conv_x(const float* __restrict__ X) {
    int i = blockIdx.x * blockDim.x + threadIdx.x;  // over NN*64 float4s
    if (i >= NN * 64) return;
    float4 v = ((const float4*)X)[i];
    __nv_bfloat16 h0 = __float2bfloat16(v.x);
    __nv_bfloat16 h1 = __float2bfloat16(v.y);
    __nv_bfloat16 h2 = __float2bfloat16(v.z);
    __nv_bfloat16 h3 = __float2bfloat16(v.w);
    __nv_bfloat16 l0 = __float2bfloat16(v.x - __bfloat162float(h0));
    __nv_bfloat16 l1 = __float2bfloat16(v.y - __bfloat162float(h1));
    __nv_bfloat16 l2 = __float2bfloat16(v.z - __bfloat162float(h2));
    __nv_bfloat16 l3 = __float2bfloat16(v.w - __bfloat162float(h3));
    *(__nv_bfloat162*)(g_Ahi + (size_t)i * 4)     = __halves2bfloat162(h0, h1);
    *(__nv_bfloat162*)(g_Ahi + (size_t)i * 4 + 2) = __halves2bfloat162(h2, h3);
    *(__nv_bfloat162*)(g_Alo + (size_t)i * 4)     = __halves2bfloat162(l0, l1);
    *(__nv_bfloat162*)(g_Alo + (size_t)i * 4 + 2) = __halves2bfloat162(l2, l3);
}

// W stored transposed: g_Bhi[n][k] (n-major, K-contiguous) for the MMA B operand
__global__ void k_conv_w(const float* __restrict__ Wl1, const float* __restrict__ Wr1) {
    int i = blockIdx.x * blockDim.x + threadIdx.x;
    if (i >= 512 * 256) return;
    int n = i >> 8, k = i & 255;
    float v = (n < 256) ? Wl1[k * 256 + n] : Wr1[k * 256 + (n - 256)];
    __nv_bfloat16 h = __float2bfloat16(v);
    g_Bhi[n * 256 + k] = h;
    g_Blo[n * 256 + k] = __float2bfloat16(v - __bfloat162float(h));
}

// ---------------- CSR build (dst-sorted) ----------------
__global__ void k_hist(const int* __restrict__ ei) {
    int i = blockIdx.x * blockDim.x + threadIdx.x;
    if (i >= E2) return;
    int dd = (i < EE) ? ei[EE + i] : (i - EE);
    atomicAdd(&g_counts[dd], 1);
}

#define SCAN_BLOCKS 49

__global__ void k_scan1() {
    __shared__ int wsum[32];
    int tid = threadIdx.x;
    int lane = tid & 31, w = tid >> 5;
    int i = blockIdx.x * 1024 + tid;
    int v = (i < NN) ? g_counts[i] : 0;
    int x = v;
#pragma unroll
    for (int st = 1; st < 32; st <<= 1) {
        int y = __shfl_up_sync(0xffffffffu, x, st);
        if (lane >= st) x += y;
    }
    if (lane == 31) wsum[w] = x;
    __syncthreads();
    if (w == 0) {
        int s = wsum[lane];
#pragma unroll
        for (int st = 1; st < 32; st <<= 1) {
            int y = __shfl_up_sync(0xffffffffu, s, st);
            if (lane >= st) s += y;
        }
        wsum[lane] = s;
    }
    __syncthreads();
    int off = (w > 0) ? wsum[w - 1] : 0;
    int incl = x + off;
    if (i < NN) g_rowptr[i] = incl - v;
    if (tid == 1023) g_bsum[blockIdx.x] = incl;
}

__global__ void k_scan2() {
    if (threadIdx.x == 0) {
        int acc = 0;
        for (int b = 0; b < SCAN_BLOCKS; b++) { g_boff[b] = acc; acc += g_bsum[b]; }
        g_rowptr[NN] = acc;
    }
}

__global__ void k_scan3() {
    int i = blockIdx.x * 1024 + threadIdx.x;
    int off = g_boff[blockIdx.x];
    if (i < NN && blockIdx.x > 0) g_rowptr[i] += off;
}

__global__ void k_scatter(const int* __restrict__ ei) {
    int i = blockIdx.x * blockDim.x + threadIdx.x;
    if (i >= E2) return;
    int s  = (i < EE) ? ei[i]      : (i - EE);
    int dd = (i < EE) ? ei[EE + i] : (i - EE);
    int pos = g_rowptr[dd] + atomicAdd(&g_fill[dd], 1);
    g_esrc[pos] = s;
}

// ---------------- GEMM1 (mma.sync bf16 hi/lo): 3 accumulating passes ----------------
// block tile 128x128, warp tile 64x32 (2x4 warp grid), BK=32, 24 chunks.
#define ASTRIDE 40  // bf16 elems per smem row (80B: 16B-aligned, bank-conflict-free)

__global__ void __launch_bounds__(256) k_gemm1_mma() {
    __shared__ __align__(16) __nv_bfloat16 sA[2][128 * ASTRIDE];
    __shared__ __align__(16) __nv_bfloat16 sB[2][128 * ASTRIDE];
    int t = threadIdx.x, lane = t & 31, w = t >> 5;
    int wm = w & 1, wn = w >> 1;
    int m0 = blockIdx.x * 128;
    int n0 = blockIdx.y * 128;

    float acc[4][4][4];
#pragma unroll
    for (int i = 0; i < 4; i++)
#pragma unroll
        for (int j = 0; j < 4; j++)
#pragma unroll
            for (int q = 0; q < 4; q++) acc[i][j][q] = 0.f;

    // chunk c (0..23): pass = c/8 (0:AhiBhi 1:AloBhi 2:AhiBlo), kk = (c%8)*32
    auto issue_load = [&](int c, int s) {
        int pass = c >> 3, kk = (c & 7) * 32;
        const __nv_bfloat16* Asrc = (pass == 1) ? g_Alo : g_Ahi;
        const __nv_bfloat16* Bsrc = (pass == 2) ? g_Blo : g_Bhi;
#pragma unroll
        for (int q = 0; q < 2; q++) {
            int idx = t + q * 256;
            int row = idx >> 2, gi = idx & 3;
            int gm = m0 + row;
            gm = gm < NN ? gm : NN - 1;
            cpa16(smem_u32(&sA[s][row * ASTRIDE + gi * 8]),
                  Asrc + (size_t)gm * 256 + kk + gi * 8);
        }
#pragma unroll
        for (int q = 0; q < 2; q++) {
            int idx = t + q * 256;
            int row = idx >> 2, gi = idx & 3;
            cpa16(smem_u32(&sB[s][row * ASTRIDE + gi * 8]),
                  Bsrc + (size_t)(n0 + row) * 256 + kk + gi * 8);
        }
        asm volatile("cp.async.commit_group;" ::: "memory");
    };

    issue_load(0, 0);
    issue_load(1, 1);

    for (int c = 0; c < 24; c++) {
        int s = c & 1;
        if (c < 23) cpwait<1>(); else cpwait<0>();
        __syncthreads();
#pragma unroll
        for (int ks = 0; ks < 2; ks++) {
            uint32_t a[4][4];
#pragma unroll
            for (int mf = 0; mf < 4; mf++) {
                uint32_t addr = smem_u32(
                    &sA[s][(wm * 64 + mf * 16 + (lane & 15)) * ASTRIDE + ks * 16 +
                           (lane >> 4) * 8]);
                ldm4(a[mf], addr);
            }
            uint32_t b[2][4];
#pragma unroll
            for (int p = 0; p < 2; p++) {
                uint32_t addr = smem_u32(
                    &sB[s][(wn * 32 + p * 16 + (lane & 7) + ((lane >> 4) & 1) * 8) *
                               ASTRIDE +
                           ks * 16 + ((lane >> 3) & 1) * 8]);
                ldm4(b[p], addr);
            }
#pragma unroll
            for (int mf = 0; mf < 4; mf++)
#pragma unroll
                for (int nf = 0; nf < 4; nf++) {
                    int p = nf >> 1, hi = (nf & 1) * 2;
                    mma16816(acc[mf][nf], a[mf], b[p][hi], b[p][hi + 1]);
                }
        }
        __syncthreads();
        if (c + 2 < 24) issue_load(c + 2, s);
    }

    // epilogue: add bias, write to g_xl1/g_xr1
#pragma unroll
    for (int mf = 0; mf < 4; mf++) {
        int row0 = m0 + wm * 64 + mf * 16 + (lane >> 2);
#pragma unroll
        for (int nf = 0; nf < 4; nf++) {
            int col = n0 + wn * 32 + nf * 8 + (lane & 3) * 2;
            float b0 = g_bcat1[col], b1 = g_bcat1[col + 1];
            float* base = (col < 256) ? g_xl1 : g_xr1;
            int cc = (col < 256) ? col : col - 256;
            if (row0 < NN) {
                float2 v = make_float2(acc[mf][nf][0] + b0, acc[mf][nf][1] + b1);
                *(float2*)(base + (size_t)row0 * 256 + cc) = v;
            }
            if (row0 + 8 < NN) {
                float2 v = make_float2(acc[mf][nf][2] + b0, acc[mf][nf][3] + b1);
                *(float2*)(base + (size_t)(row0 + 8) * 256 + cc) = v;
            }
        }
    }
}

// ---------------- layer-1 edge phase: warp per dst node, online softmax, pipelined ----------------
__global__ void __launch_bounds__(256) k_edge1(const float* __restrict__ att1,
                                               const float* __restrict__ bias1) {
    int gw = (blockIdx.x * blockDim.x + threadIdx.x) >> 5;
    int lane = threadIdx.x & 31;
    if (gw >= NN) return;
    int d = gw;
    int cb = lane * 8;  // 8 channels per lane; head = lane>>3
    const float4* xrp = (const float4*)(g_xr1 + (size_t)d * 256 + cb);
    float4 xr0 = xrp[0], xr1v = xrp[1];
    const float4* ap = (const float4*)(att1 + cb);
    float4 at0 = ap[0], at1 = ap[1];
    int p0 = g_rowptr[d], p1 = g_rowptr[d + 1];

    float m = -INFINITY, denom = 0.f;
    float4 acc0 = make_float4(0.f, 0.f, 0.f, 0.f), acc1 = acc0;

    // prefetch edge p0
    int s = g_esrc[p0];
    const float4* xs = (const float4*)(g_xl1 + (size_t)s * 256 + cb);
    float4 a0 = xs[0], a1 = xs[1];

    for (int p = p0; p < p1; p++) {
        float4 c0 = a0, c1 = a1;
        if (p + 1 < p1) {  // prefetch next edge's row before the reduce chain
            int s2 = g_esrc[p + 1];
            const float4* xn = (const float4*)(g_xl1 + (size_t)s2 * 256 + cb);
            a0 = xn[0];
            a1 = xn[1];
        }
        float pa = lrelu(c0.x + xr0.x) * at0.x + lrelu(c0.y + xr0.y) * at0.y +
                   lrelu(c0.z + xr0.z) * at0.z + lrelu(c0.w + xr0.w) * at0.w +
                   lrelu(c1.x + xr1v.x) * at1.x + lrelu(c1.y + xr1v.y) * at1.y +
                   lrelu(c1.z + xr1v.z) * at1.z + lrelu(c1.w + xr1v.w) * at1.w;
        pa += __shfl_xor_sync(0xffffffffu, pa, 1);
        pa += __shfl_xor_sync(0xffffffffu, pa, 2);
        pa += __shfl_xor_sync(0xffffffffu, pa, 4);
        // online softmax update (per-head; all 8 lanes of a head agree on pa/m)
        if (pa > m) {
            float sc = __expf(m - pa);  // first time: exp(-inf)=0
            denom *= sc;
            acc0.x *= sc; acc0.y *= sc; acc0.z *= sc; acc0.w *= sc;
            acc1.x *= sc; acc1.y *= sc; acc1.z *= sc; acc1.w *= sc;
            m = pa;
        }
        float ee = __expf(pa - m);
        denom += ee;
        acc0.x += ee * c0.x; acc0.y += ee * c0.y; acc0.z += ee * c0.z; acc0.w += ee * c0.w;
        acc1.x += ee * c1.x; acc1.y += ee * c1.y; acc1.z += ee * c1.z; acc1.w += ee * c1.w;
    }
    float inv = 1.f / (denom + 1e-16f);
    const float4* bp = (const float4*)(bias1 + cb);
    float4 b0 = bp[0], b1 = bp[1];
    float4 o0, o1;
    o0.x = tanhf(acc0.x * inv + b0.x); o0.y = tanhf(acc0.y * inv + b0.y);
    o0.z = tanhf(acc0.z * inv + b0.z); o0.w = tanhf(acc0.w * inv + b0.w);
    o1.x = tanhf(acc1.x * inv + b1.x); o1.y = tanhf(acc1.y * inv + b1.y);
    o1.z = tanhf(acc1.z * inv + b1.z); o1.w = tanhf(acc1.w * inv + b1.w);
    float4* hp = (float4*)(g_h1 + (size_t)d * 256 + cb);
    hp[0] = o0; hp[1] = o1;
}

// ---------------- GEMM2 ----------------
__global__ void k_gemm2() {
    __shared__ float Ws[256 * 32];
    int t = threadIdx.x;
    for (int i = t; i < 256 * 32; i += 256) Ws[i] = g_Wcat2[i];
    __syncthreads();
    int warp = t >> 5, lane = t & 31;
    int row = blockIdx.x * 8 + warp;
    if (row >= NN) return;
    float acc = 0.f;
    const float* hrow = g_h1 + (size_t)row * 256;
    for (int k0 = 0; k0 < 256; k0 += 32) {
        float hv = hrow[k0 + lane];
#pragma unroll
        for (int j = 0; j < 32; j++) {
            float hb = __shfl_sync(0xffffffffu, hv, j);
            acc += hb * Ws[(k0 + j) * 32 + lane];
        }
    }
    float v = acc + g_bcat2[lane];
    if (lane < 16) g_xl2[(size_t)row * 16 + lane] = v;
    else           g_xr2[(size_t)row * 16 + (lane - 16)] = v;
}

// ---------------- layer-2 edge phase + log_softmax: online softmax, pipelined ----------------
__global__ void __launch_bounds__(256) k_edge2(const float* __restrict__ att2,
                                               const float* __restrict__ bias2,
                                               float* __restrict__ outO,
                                               float* __restrict__ outLP) {
    int gw = (blockIdx.x * blockDim.x + threadIdx.x) >> 5;
    int lane = threadIdx.x & 31;
    if (gw >= NN) return;
    int d = gw;
    int c = lane & 15;  // both 16-lane halves mirror the same work
    float xrv = g_xr2[(size_t)d * 16 + c];
    float av = att2[c];
    int p0 = g_rowptr[d], p1 = g_rowptr[d + 1];

    float m = -INFINITY, denom = 0.f, acc = 0.f;

    int s = g_esrc[p0];
    float xv = g_xl2[(size_t)s * 16 + c];

    for (int p = p0; p < p1; p++) {
        float cx = xv;
        if (p + 1 < p1) {
            int s2 = g_esrc[p + 1];
            xv = g_xl2[(size_t)s2 * 16 + c];
        }
        float v = cx + xrv;
        v = v > 0.f ? v : 0.2f * v;
        float pa = v * av;
        pa += __shfl_xor_sync(0xffffffffu, pa, 1);
        pa += __shfl_xor_sync(0xffffffffu, pa, 2);
        pa += __shfl_xor_sync(0xffffffffu, pa, 4);
        pa += __shfl_xor_sync(0xffffffffu, pa, 8);
        if (pa > m) {
            float sc = __expf(m - pa);
            denom *= sc;
            acc *= sc;
            m = pa;
        }
        float ee = __expf(pa - m);
        denom += ee;
        acc += ee * cx;
    }
    float o = acc / (denom + 1e-16f) + bias2[c];

    // log_softmax over the 16 channels (within each 16-lane half)
    float mm = o;
    mm = fmaxf(mm, __shfl_xor_sync(0xffffffffu, mm, 1));
    mm = fmaxf(mm, __shfl_xor_sync(0xffffffffu, mm, 2));
    mm = fmaxf(mm, __shfl_xor_sync(0xffffffffu, mm, 4));
    mm = fmaxf(mm, __shfl_xor_sync(0xffffffffu, mm, 8));
    float se = __expf(o - mm);
    se += __shfl_xor_sync(0xffffffffu, se, 1);
    se += __shfl_xor_sync(0xffffffffu, se, 2);
    se += __shfl_xor_sync(0xffffffffu, se, 4);
    se += __shfl_xor_sync(0xffffffffu, se, 8);
    float lp = o - mm - logf(se);

    if (lane < 16) {
        outO[(size_t)d * 16 + c] = o;
        if (outLP) outLP[(size_t)d * 16 + c] = lp;
    }
}

// ---------------- launch ----------------
extern "C" void kernel_launch(void* const* d_in, const int* in_sizes, int n_in,
                              void* d_out, int out_size) {
    const float* x     = (const float*)d_in[0];
    const int*   ei    = (const int*)d_in[1];
    const float* Wl1   = (const float*)d_in[2];
    const float* bl1   = (const float*)d_in[3];
    const float* Wr1   = (const float*)d_in[4];
    const float* br1   = (const float*)d_in[5];
    const float* att1  = (const float*)d_in[6];
    const float* bias1 = (const float*)d_in[7];
    const float* Wl2   = (const float*)d_in[8];
    const float* bl2   = (const float*)d_in[9];
    const float* Wr2   = (const float*)d_in[10];
    const float* br2   = (const float*)d_in[11];
    const float* att2  = (const float*)d_in[12];
    const float* bias2 = (const float*)d_in[13];

    float* outO  = (float*)d_out;
    float* outLP = (out_size >= 2 * NN * OUTD) ? ((float*)d_out + NN * OUTD) : nullptr;

    // GEMM1 deps first so k_gemm1_mma lands at launch index 3 (the profiled slot).
    k_conv_x<<<(NN * 64 + 255) / 256, 256>>>(x);
    k_conv_w<<<512, 256>>>(Wl1, Wr1);
    k_prep<<<32, 256>>>(bl1, br1, Wl2, bl2, Wr2, br2);
    dim3 g1(MTILES, 4);
    k_gemm1_mma<<<g1, 256>>>();

    k_zero<<<(NN + 255) / 256, 256>>>();
    k_hist<<<(E2 + 255) / 256, 256>>>(ei);
    k_scan1<<<SCAN_BLOCKS, 1024>>>();
    k_scan2<<<1, 32>>>();
    k_scan3<<<SCAN_BLOCKS, 1024>>>();
    k_scatter<<<(E2 + 255) / 256, 256>>>(ei);

    k_edge1<<<(NN + 7) / 8, 256>>>(att1, bias1);
    k_gemm2<<<(NN + 7) / 8, 256>>>();
    k_edge2<<<(NN + 7) / 8, 256>>>(att2, bias2, outO, outLP);
}

// round 7
// speedup vs baseline: 1.5305x; 1.0362x over previous
#include <cuda_runtime.h>
#include <cuda_bf16.h>
#include <math.h>
#include <stdint.h>

#define NN 50000
#define EE 400000
#define E2 (EE + NN)
#define OUTD 16
#define MTILES 391  // ceil(50000/128)

// ---------------- scratch (device globals; no allocs allowed) ----------------
__device__ __align__(16) float g_xl1[NN * 256];
__device__ __align__(16) float g_xr1[NN * 256];
__device__ __align__(16) float g_h1[NN * 256];
__device__ __align__(16) float g_xl2[NN * OUTD];
__device__ __align__(16) float g_xr2[NN * OUTD];
__device__ int g_esrc[E2];
__device__ int g_counts[NN];
__device__ int g_fill[NN];
__device__ int g_rowptr[NN + 1];
__device__ int g_bsum[64];
__device__ int g_boff[64];
__device__ __align__(16) float g_bcat1[512];
__device__ __align__(16) float g_Wcat2[256 * 32];
__device__ __align__(16) float g_bcat2[32];
// bf16 hi/lo split operands for tensor-core GEMM1
__device__ __align__(16) __nv_bfloat16 g_Ahi[NN * 256];
__device__ __align__(16) __nv_bfloat16 g_Alo[NN * 256];
__device__ __align__(16) __nv_bfloat16 g_Bhi[512 * 256];
__device__ __align__(16) __nv_bfloat16 g_Blo[512 * 256];

__device__ __forceinline__ float lrelu(float v) { return v > 0.f ? v : 0.2f * v; }

// ---------------- PTX helpers (arch-portable: ldmatrix + mma.sync) ----------------
__device__ __forceinline__ uint32_t smem_u32(const void* p) {
    uint32_t a;
    asm("{ .reg .u64 t; cvta.to.shared.u64 t, %1; cvt.u32.u64 %0, t; }"
        : "=r"(a) : "l"(p));
    return a;
}
__device__ __forceinline__ void cpa16(uint32_t dst, const void* src) {
    asm volatile("cp.async.cg.shared.global [%0], [%1], 16;" ::"r"(dst), "l"(src)
                 : "memory");
}
template <int N>
__device__ __forceinline__ void cpwait() {
    asm volatile("cp.async.wait_group %0;" ::"n"(N) : "memory");
}
__device__ __forceinline__ void ldm4(uint32_t* r, uint32_t addr) {
    asm volatile("ldmatrix.sync.aligned.m8n8.x4.shared.b16 {%0,%1,%2,%3}, [%4];"
                 : "=r"(r[0]), "=r"(r[1]), "=r"(r[2]), "=r"(r[3])
                 : "r"(addr));
}
__device__ __forceinline__ void mma16816(float* c, const uint32_t* a, uint32_t b0,
                                         uint32_t b1) {
    asm volatile(
        "mma.sync.aligned.m16n8k16.row.col.f32.bf16.bf16.f32 "
        "{%0,%1,%2,%3}, {%4,%5,%6,%7}, {%8,%9}, {%0,%1,%2,%3};"
        : "+f"(c[0]), "+f"(c[1]), "+f"(c[2]), "+f"(c[3])
        : "r"(a[0]), "r"(a[1]), "r"(a[2]), "r"(a[3]), "r"(b0), "r"(b1));
}

// ---------------- init ----------------
__global__ void k_zero() {
    int i = blockIdx.x * blockDim.x + threadIdx.x;
    if (i < NN) { g_counts[i] = 0; g_fill[i] = 0; }
}

__global__ void k_prep(const float* __restrict__ bl1, const float* __restrict__ br1,
                       const float* __restrict__ Wl2, const float* __restrict__ bl2,
                       const float* __restrict__ Wr2, const float* __restrict__ br2) {
    for (int i = blockIdx.x * blockDim.x + threadIdx.x; i < 256 * 32;
         i += gridDim.x * blockDim.x) {
        int k2 = i >> 5, n2 = i & 31;
        g_Wcat2[i] = (n2 < 16) ? Wl2[k2 * 16 + n2] : Wr2[k2 * 16 + (n2 - 16)];
        if (i < 512) g_bcat1[i] = (i < 256) ? bl1[i] : br1[i - 256];
        if (i < 32) g_bcat2[i] = (i < 16) ? bl2[i] : br2[i - 16];
    }
}

// ---------------- bf16 hi/lo conversions ----------------
__global__ void k_conv_x(const float* __restrict__ X) {
    int i = blockIdx.x * blockDim.x + threadIdx.x;  // over NN*64 float4s
    if (i >= NN * 64) return;
    float4 v = ((const float4*)X)[i];
    __nv_bfloat16 h0 = __float2bfloat16(v.x);
    __nv_bfloat16 h1 = __float2bfloat16(v.y);
    __nv_bfloat16 h2 = __float2bfloat16(v.z);
    __nv_bfloat16 h3 = __float2bfloat16(v.w);
    __nv_bfloat16 l0 = __float2bfloat16(v.x - __bfloat162float(h0));
    __nv_bfloat16 l1 = __float2bfloat16(v.y - __bfloat162float(h1));
    __nv_bfloat16 l2 = __float2bfloat16(v.z - __bfloat162float(h2));
    __nv_bfloat16 l3 = __float2bfloat16(v.w - __bfloat162float(h3));
    *(__nv_bfloat162*)(g_Ahi + (size_t)i * 4)     = __halves2bfloat162(h0, h1);
    *(__nv_bfloat162*)(g_Ahi + (size_t)i * 4 + 2) = __halves2bfloat162(h2, h3);
    *(__nv_bfloat162*)(g_Alo + (size_t)i * 4)     = __halves2bfloat162(l0, l1);
    *(__nv_bfloat162*)(g_Alo + (size_t)i * 4 + 2) = __halves2bfloat162(l2, l3);
}

// W stored transposed: g_Bhi[n][k] (n-major, K-contiguous) for the MMA B operand
__global__ void k_conv_w(const float* __restrict__ Wl1, const float* __restrict__ Wr1) {
    int i = blockIdx.x * blockDim.x + threadIdx.x;
    if (i >= 512 * 256) return;
    int n = i >> 8, k = i & 255;
    float v = (n < 256) ? Wl1[k * 256 + n] : Wr1[k * 256 + (n - 256)];
    __nv_bfloat16 h = __float2bfloat16(v);
    g_Bhi[n * 256 + k] = h;
    g_Blo[n * 256 + k] = __float2bfloat16(v - __bfloat162float(h));
}

// ---------------- CSR build (dst-sorted) ----------------
__global__ void k_hist(const int* __restrict__ ei) {
    int i = blockIdx.x * blockDim.x + threadIdx.x;
    if (i >= E2) return;
    int dd = (i < EE) ? ei[EE + i] : (i - EE);
    atomicAdd(&g_counts[dd], 1);
}

#define SCAN_BLOCKS 49

__global__ void k_scan1() {
    __shared__ int wsum[32];
    int tid = threadIdx.x;
    int lane = tid & 31, w = tid >> 5;
    int i = blockIdx.x * 1024 + tid;
    int v = (i < NN) ? g_counts[i] : 0;
    int x = v;
#pragma unroll
    for (int st = 1; st < 32; st <<= 1) {
        int y = __shfl_up_sync(0xffffffffu, x, st);
        if (lane >= st) x += y;
    }
    if (lane == 31) wsum[w] = x;
    __syncthreads();
    if (w == 0) {
        int s = wsum[lane];
#pragma unroll
        for (int st = 1; st < 32; st <<= 1) {
            int y = __shfl_up_sync(0xffffffffu, s, st);
            if (lane >= st) s += y;
        }
        wsum[lane] = s;
    }
    __syncthreads();
    int off = (w > 0) ? wsum[w - 1] : 0;
    int incl = x + off;
    if (i < NN) g_rowptr[i] = incl - v;
    if (tid == 1023) g_bsum[blockIdx.x] = incl;
}

__global__ void k_scan2() {
    if (threadIdx.x == 0) {
        int acc = 0;
        for (int b = 0; b < SCAN_BLOCKS; b++) { g_boff[b] = acc; acc += g_bsum[b]; }
        g_rowptr[NN] = acc;
    }
}

__global__ void k_scan3() {
    int i = blockIdx.x * 1024 + threadIdx.x;
    int off = g_boff[blockIdx.x];
    if (i < NN && blockIdx.x > 0) g_rowptr[i] += off;
}

__global__ void k_scatter(const int* __restrict__ ei) {
    int i = blockIdx.x * blockDim.x + threadIdx.x;
    if (i >= E2) return;
    int s  = (i < EE) ? ei[i]      : (i - EE);
    int dd = (i < EE) ? ei[EE + i] : (i - EE);
    int pos = g_rowptr[dd] + atomicAdd(&g_fill[dd], 1);
    g_esrc[pos] = s;
}

// ---------------- GEMM1 (mma.sync bf16 hi/lo): 3 accumulating passes ----------------
// block tile 128x128, warp tile 64x32 (2x4 warp grid), BK=32, 24 chunks.
// 4-stage cp.async pipeline in dynamic smem (80KB), one barrier per chunk.
#define ASTRIDE 40        // bf16 elems per smem row (80B: 16B-aligned, conflict-free)
#define STAGEB 20480      // (sA + sB) bytes per stage = 2 * 128*40*2
#define NSTAGE 4
#define GDYN (NSTAGE * STAGEB)

__global__ void __launch_bounds__(256) k_gemm1_mma() {
    extern __shared__ __align__(16) char dsm[];
    int t = threadIdx.x, lane = t & 31, w = t >> 5;
    int wm = w & 1, wn = w >> 1;
    int m0 = blockIdx.x * 128;
    int n0 = blockIdx.y * 128;
    uint32_t sbase = smem_u32(dsm);

    float acc[4][4][4];
#pragma unroll
    for (int i = 0; i < 4; i++)
#pragma unroll
        for (int j = 0; j < 4; j++)
#pragma unroll
            for (int q = 0; q < 4; q++) acc[i][j][q] = 0.f;

    // chunk c (0..23): pass = c/8 (0:AhiBhi 1:AloBhi 2:AhiBlo), kk = (c%8)*32
    auto issue_load = [&](int c) {
        int st = c & (NSTAGE - 1);
        int pass = c >> 3, kk = (c & 7) * 32;
        const __nv_bfloat16* Asrc = (pass == 1) ? g_Alo : g_Ahi;
        const __nv_bfloat16* Bsrc = (pass == 2) ? g_Blo : g_Bhi;
        uint32_t sa = sbase + st * STAGEB;
        uint32_t sb = sa + 10240;
        {
            int row = t >> 1, gi = t & 1;  // 256 threads: rows 0..127, 2x32B? no:
        }
        // A tile: 128 rows x 32 cols bf16 = 64B/row = 4 granules; 512 granules total
#pragma unroll
        for (int q = 0; q < 2; q++) {
            int idx = t + q * 256;
            int row = idx >> 2, gi = idx & 3;
            int gm = m0 + row;
            gm = gm < NN ? gm : NN - 1;
            cpa16(sa + (row * ASTRIDE + gi * 8) * 2,
                  Asrc + (size_t)gm * 256 + kk + gi * 8);
        }
#pragma unroll
        for (int q = 0; q < 2; q++) {
            int idx = t + q * 256;
            int row = idx >> 2, gi = idx & 3;
            cpa16(sb + (row * ASTRIDE + gi * 8) * 2,
                  Bsrc + (size_t)(n0 + row) * 256 + kk + gi * 8);
        }
        asm volatile("cp.async.commit_group;" ::: "memory");
    };

    issue_load(0);
    issue_load(1);
    issue_load(2);

    for (int c = 0; c < 24; c++) {
        int st = c & (NSTAGE - 1);
        cpwait<2>();
        __syncthreads();
        if (c + 3 < 24) issue_load(c + 3);  // target stage last read at iter c-1
        uint32_t sa = sbase + st * STAGEB;
        uint32_t sb = sa + 10240;
#pragma unroll
        for (int ks = 0; ks < 2; ks++) {
            uint32_t a[4][4];
#pragma unroll
            for (int mf = 0; mf < 4; mf++) {
                uint32_t addr = sa + ((wm * 64 + mf * 16 + (lane & 15)) * ASTRIDE +
                                      ks * 16 + (lane >> 4) * 8) *
                                         2;
                ldm4(a[mf], addr);
            }
            uint32_t b[2][4];
#pragma unroll
            for (int p = 0; p < 2; p++) {
                uint32_t addr =
                    sb + ((wn * 32 + p * 16 + (lane & 7) + ((lane >> 4) & 1) * 8) *
                              ASTRIDE +
                          ks * 16 + ((lane >> 3) & 1) * 8) *
                             2;
                ldm4(b[p], addr);
            }
#pragma unroll
            for (int mf = 0; mf < 4; mf++)
#pragma unroll
                for (int nf = 0; nf < 4; nf++) {
                    int p = nf >> 1, hi = (nf & 1) * 2;
                    mma16816(acc[mf][nf], a[mf], b[p][hi], b[p][hi + 1]);
                }
        }
    }

    // epilogue: add bias, write to g_xl1/g_xr1
#pragma unroll
    for (int mf = 0; mf < 4; mf++) {
        int row0 = m0 + wm * 64 + mf * 16 + (lane >> 2);
#pragma unroll
        for (int nf = 0; nf < 4; nf++) {
            int col = n0 + wn * 32 + nf * 8 + (lane & 3) * 2;
            float b0 = g_bcat1[col], b1 = g_bcat1[col + 1];
            float* base = (col < 256) ? g_xl1 : g_xr1;
            int cc = (col < 256) ? col : col - 256;
            if (row0 < NN) {
                float2 v = make_float2(acc[mf][nf][0] + b0, acc[mf][nf][1] + b1);
                *(float2*)(base + (size_t)row0 * 256 + cc) = v;
            }
            if (row0 + 8 < NN) {
                float2 v = make_float2(acc[mf][nf][2] + b0, acc[mf][nf][3] + b1);
                *(float2*)(base + (size_t)(row0 + 8) * 256 + cc) = v;
            }
        }
    }
}

// ---------------- layer-1 edge phase: warp per dst node, online softmax, pipelined ----------------
__global__ void __launch_bounds__(256) k_edge1(const float* __restrict__ att1,
                                               const float* __restrict__ bias1) {
    int gw = (blockIdx.x * blockDim.x + threadIdx.x) >> 5;
    int lane = threadIdx.x & 31;
    if (gw >= NN) return;
    int d = gw;
    int cb = lane * 8;  // 8 channels per lane; head = lane>>3
    const float4* xrp = (const float4*)(g_xr1 + (size_t)d * 256 + cb);
    float4 xr0 = xrp[0], xr1v = xrp[1];
    const float4* ap = (const float4*)(att1 + cb);
    float4 at0 = ap[0], at1 = ap[1];
    int p0 = g_rowptr[d], p1 = g_rowptr[d + 1];

    float m = -INFINITY, denom = 0.f;
    float4 acc0 = make_float4(0.f, 0.f, 0.f, 0.f), acc1 = acc0;

    // prefetch edge p0
    int s = g_esrc[p0];
    const float4* xs = (const float4*)(g_xl1 + (size_t)s * 256 + cb);
    float4 a0 = xs[0], a1 = xs[1];

    for (int p = p0; p < p1; p++) {
        float4 c0 = a0, c1 = a1;
        if (p + 1 < p1) {  // prefetch next edge's row before the reduce chain
            int s2 = g_esrc[p + 1];
            const float4* xn = (const float4*)(g_xl1 + (size_t)s2 * 256 + cb);
            a0 = xn[0];
            a1 = xn[1];
        }
        float pa = lrelu(c0.x + xr0.x) * at0.x + lrelu(c0.y + xr0.y) * at0.y +
                   lrelu(c0.z + xr0.z) * at0.z + lrelu(c0.w + xr0.w) * at0.w +
                   lrelu(c1.x + xr1v.x) * at1.x + lrelu(c1.y + xr1v.y) * at1.y +
                   lrelu(c1.z + xr1v.z) * at1.z + lrelu(c1.w + xr1v.w) * at1.w;
        pa += __shfl_xor_sync(0xffffffffu, pa, 1);
        pa += __shfl_xor_sync(0xffffffffu, pa, 2);
        pa += __shfl_xor_sync(0xffffffffu, pa, 4);
        // online softmax update (per-head; all 8 lanes of a head agree on pa/m)
        if (pa > m) {
            float sc = __expf(m - pa);  // first time: exp(-inf)=0
            denom *= sc;
            acc0.x *= sc; acc0.y *= sc; acc0.z *= sc; acc0.w *= sc;
            acc1.x *= sc; acc1.y *= sc; acc1.z *= sc; acc1.w *= sc;
            m = pa;
        }
        float ee = __expf(pa - m);
        denom += ee;
        acc0.x += ee * c0.x; acc0.y += ee * c0.y; acc0.z += ee * c0.z; acc0.w += ee * c0.w;
        acc1.x += ee * c1.x; acc1.y += ee * c1.y; acc1.z += ee * c1.z; acc1.w += ee * c1.w;
    }
    float inv = 1.f / (denom + 1e-16f);
    const float4* bp = (const float4*)(bias1 + cb);
    float4 b0 = bp[0], b1 = bp[1];
    float4 o0, o1;
    o0.x = tanhf(acc0.x * inv + b0.x); o0.y = tanhf(acc0.y * inv + b0.y);
    o0.z = tanhf(acc0.z * inv + b0.z); o0.w = tanhf(acc0.w * inv + b0.w);
    o1.x = tanhf(acc1.x * inv + b1.x); o1.y = tanhf(acc1.y * inv + b1.y);
    o1.z = tanhf(acc1.z * inv + b1.z); o1.w = tanhf(acc1.w * inv + b1.w);
    float4* hp = (float4*)(g_h1 + (size_t)d * 256 + cb);
    hp[0] = o0; hp[1] = o1;
}

// ---------------- GEMM2 ----------------
__global__ void k_gemm2() {
    __shared__ float Ws[256 * 32];
    int t = threadIdx.x;
    for (int i = t; i < 256 * 32; i += 256) Ws[i] = g_Wcat2[i];
    __syncthreads();
    int warp = t >> 5, lane = t & 31;
    int row = blockIdx.x * 8 + warp;
    if (row >= NN) return;
    float acc = 0.f;
    const float* hrow = g_h1 + (size_t)row * 256;
    for (int k0 = 0; k0 < 256; k0 += 32) {
        float hv = hrow[k0 + lane];
#pragma unroll
        for (int j = 0; j < 32; j++) {
            float hb = __shfl_sync(0xffffffffu, hv, j);
            acc += hb * Ws[(k0 + j) * 32 + lane];
        }
    }
    float v = acc + g_bcat2[lane];
    if (lane < 16) g_xl2[(size_t)row * 16 + lane] = v;
    else           g_xr2[(size_t)row * 16 + (lane - 16)] = v;
}

// ---------------- layer-2 edge phase + log_softmax: online softmax, pipelined ----------------
__global__ void __launch_bounds__(256) k_edge2(const float* __restrict__ att2,
                                               const float* __restrict__ bias2,
                                               float* __restrict__ outO,
                                               float* __restrict__ outLP) {
    int gw = (blockIdx.x * blockDim.x + threadIdx.x) >> 5;
    int lane = threadIdx.x & 31;
    if (gw >= NN) return;
    int d = gw;
    int c = lane & 15;  // both 16-lane halves mirror the same work
    float xrv = g_xr2[(size_t)d * 16 + c];
    float av = att2[c];
    int p0 = g_rowptr[d], p1 = g_rowptr[d + 1];

    float m = -INFINITY, denom = 0.f, acc = 0.f;

    int s = g_esrc[p0];
    float xv = g_xl2[(size_t)s * 16 + c];

    for (int p = p0; p < p1; p++) {
        float cx = xv;
        if (p + 1 < p1) {
            int s2 = g_esrc[p + 1];
            xv = g_xl2[(size_t)s2 * 16 + c];
        }
        float v = cx + xrv;
        v = v > 0.f ? v : 0.2f * v;
        float pa = v * av;
        pa += __shfl_xor_sync(0xffffffffu, pa, 1);
        pa += __shfl_xor_sync(0xffffffffu, pa, 2);
        pa += __shfl_xor_sync(0xffffffffu, pa, 4);
        pa += __shfl_xor_sync(0xffffffffu, pa, 8);
        if (pa > m) {
            float sc = __expf(m - pa);
            denom *= sc;
            acc *= sc;
            m = pa;
        }
        float ee = __expf(pa - m);
        denom += ee;
        acc += ee * cx;
    }
    float o = acc / (denom + 1e-16f) + bias2[c];

    // log_softmax over the 16 channels (within each 16-lane half)
    float mm = o;
    mm = fmaxf(mm, __shfl_xor_sync(0xffffffffu, mm, 1));
    mm = fmaxf(mm, __shfl_xor_sync(0xffffffffu, mm, 2));
    mm = fmaxf(mm, __shfl_xor_sync(0xffffffffu, mm, 4));
    mm = fmaxf(mm, __shfl_xor_sync(0xffffffffu, mm, 8));
    float se = __expf(o - mm);
    se += __shfl_xor_sync(0xffffffffu, se, 1);
    se += __shfl_xor_sync(0xffffffffu, se, 2);
    se += __shfl_xor_sync(0xffffffffu, se, 4);
    se += __shfl_xor_sync(0xffffffffu, se, 8);
    float lp = o - mm - logf(se);

    if (lane < 16) {
        outO[(size_t)d * 16 + c] = o;
        if (outLP) outLP[(size_t)d * 16 + c] = lp;
    }
}

// ---------------- launch ----------------
extern "C" void kernel_launch(void* const* d_in, const int* in_sizes, int n_in,
                              void* d_out, int out_size) {
    const float* x     = (const float*)d_in[0];
    const int*   ei    = (const int*)d_in[1];
    const float* Wl1   = (const float*)d_in[2];
    const float* bl1   = (const float*)d_in[3];
    const float* Wr1   = (const float*)d_in[4];
    const float* br1   = (const float*)d_in[5];
    const float* att1  = (const float*)d_in[6];
    const float* bias1 = (const float*)d_in[7];
    const float* Wl2   = (const float*)d_in[8];
    const float* bl2   = (const float*)d_in[9];
    const float* Wr2   = (const float*)d_in[10];
    const float* br2   = (const float*)d_in[11];
    const float* att2  = (const float*)d_in[12];
    const float* bias2 = (const float*)d_in[13];

    float* outO  = (float*)d_out;
    float* outLP = (out_size >= 2 * NN * OUTD) ? ((float*)d_out + NN * OUTD) : nullptr;

    cudaFuncSetAttribute(k_gemm1_mma, cudaFuncAttributeMaxDynamicSharedMemorySize,
                         GDYN);

    // GEMM1 deps first so k_gemm1_mma lands at launch index 3 (the profiled slot).
    k_conv_x<<<(NN * 64 + 255) / 256, 256>>>(x);
    k_conv_w<<<512, 256>>>(Wl1, Wr1);
    k_prep<<<32, 256>>>(bl1, br1, Wl2, bl2, Wr2, br2);
    dim3 g1(MTILES, 4);
    k_gemm1_mma<<<g1, 256, GDYN>>>();

    k_zero<<<(NN + 255) / 256, 256>>>();
    k_hist<<<(E2 + 255) / 256, 256>>>(ei);
    k_scan1<<<SCAN_BLOCKS, 1024>>>();
    k_scan2<<<1, 32>>>();
    k_scan3<<<SCAN_BLOCKS, 1024>>>();
    k_scatter<<<(E2 + 255) / 256, 256>>>(ei);

    k_edge1<<<(NN + 7) / 8, 256>>>(att1, bias1);
    k_gemm2<<<(NN + 7) / 8, 256>>>();
    k_edge2<<<(NN + 7) / 8, 256>>>(att2, bias2, outO, outLP);
}

// round 8
// speedup vs baseline: 1.5938x; 1.0414x over previous
#include <cuda_runtime.h>
#include <cuda_bf16.h>
#include <math.h>
#include <stdint.h>

#define NN 50000
#define EE 400000
#define E2 (EE + NN)
#define OUTD 16
#define MTILES 391  // ceil(50000/128)

// ---------------- scratch (device globals; no allocs allowed) ----------------
__device__ __align__(16) float g_xl1[NN * 256];
__device__ __align__(16) float g_xr1[NN * 256];
__device__ __align__(16) float g_h1[NN * 256];
__device__ __align__(16) float g_xl2[NN * OUTD];
__device__ __align__(16) float g_xr2[NN * OUTD];
__device__ int g_esrc[E2];
__device__ int g_counts[NN];
__device__ int g_fill[NN];
__device__ int g_rowptr[NN + 1];
__device__ int g_bsum[64];
__device__ int g_boff[64];
__device__ __align__(16) float g_bcat1[512];
__device__ __align__(16) float g_Wcat2[256 * 32];
__device__ __align__(16) float g_bcat2[32];
// bf16 hi/lo split operands for tensor-core GEMM1
__device__ __align__(16) __nv_bfloat16 g_Ahi[NN * 256];
__device__ __align__(16) __nv_bfloat16 g_Alo[NN * 256];
__device__ __align__(16) __nv_bfloat16 g_Bhi[512 * 256];
__device__ __align__(16) __nv_bfloat16 g_Blo[512 * 256];

__device__ __forceinline__ float lrelu(float v) { return v > 0.f ? v : 0.2f * v; }

// ---------------- PTX helpers (arch-portable: ldmatrix + mma.sync) ----------------
__device__ __forceinline__ uint32_t smem_u32(const void* p) {
    uint32_t a;
    asm("{ .reg .u64 t; cvta.to.shared.u64 t, %1; cvt.u32.u64 %0, t; }"
        : "=r"(a) : "l"(p));
    return a;
}
__device__ __forceinline__ void cpa16(uint32_t dst, const void* src) {
    asm volatile("cp.async.cg.shared.global [%0], [%1], 16;" ::"r"(dst), "l"(src)
                 : "memory");
}
template <int N>
__device__ __forceinline__ void cpwait() {
    asm volatile("cp.async.wait_group %0;" ::"n"(N) : "memory");
}
__device__ __forceinline__ void ldm4(uint32_t* r, uint32_t addr) {
    asm volatile("ldmatrix.sync.aligned.m8n8.x4.shared.b16 {%0,%1,%2,%3}, [%4];"
                 : "=r"(r[0]), "=r"(r[1]), "=r"(r[2]), "=r"(r[3])
                 : "r"(addr));
}
__device__ __forceinline__ void mma16816(float* c, const uint32_t* a, uint32_t b0,
                                         uint32_t b1) {
    asm volatile(
        "mma.sync.aligned.m16n8k16.row.col.f32.bf16.bf16.f32 "
        "{%0,%1,%2,%3}, {%4,%5,%6,%7}, {%8,%9}, {%0,%1,%2,%3};"
        : "+f"(c[0]), "+f"(c[1]), "+f"(c[2]), "+f"(c[3])
        : "r"(a[0]), "r"(a[1]), "r"(a[2]), "r"(a[3]), "r"(b0), "r"(b1));
}

// ---------------- init ----------------
__global__ void k_zero() {
    int i = blockIdx.x * blockDim.x + threadIdx.x;
    if (i < NN) { g_counts[i] = 0; g_fill[i] = 0; }
}

__global__ void k_prep(const float* __restrict__ bl1, const float* __restrict__ br1,
                       const float* __restrict__ Wl2, const float* __restrict__ bl2,
                       const float* __restrict__ Wr2, const float* __restrict__ br2) {
    for (int i = blockIdx.x * blockDim.x + threadIdx.x; i < 256 * 32;
         i += gridDim.x * blockDim.x) {
        int k2 = i >> 5, n2 = i & 31;
        g_Wcat2[i] = (n2 < 16) ? Wl2[k2 * 16 + n2] : Wr2[k2 * 16 + (n2 - 16)];
        if (i < 512) g_bcat1[i] = (i < 256) ? bl1[i] : br1[i - 256];
        if (i < 32) g_bcat2[i] = (i < 16) ? bl2[i] : br2[i - 16];
    }
}

// ---------------- bf16 hi/lo conversions ----------------
__global__ void k_conv_x(const float* __restrict__ X) {
    int i = blockIdx.x * blockDim.x + threadIdx.x;  // over NN*64 float4s
    if (i >= NN * 64) return;
    float4 v = ((const float4*)X)[i];
    __nv_bfloat16 h0 = __float2bfloat16(v.x);
    __nv_bfloat16 h1 = __float2bfloat16(v.y);
    __nv_bfloat16 h2 = __float2bfloat16(v.z);
    __nv_bfloat16 h3 = __float2bfloat16(v.w);
    __nv_bfloat16 l0 = __float2bfloat16(v.x - __bfloat162float(h0));
    __nv_bfloat16 l1 = __float2bfloat16(v.y - __bfloat162float(h1));
    __nv_bfloat16 l2 = __float2bfloat16(v.z - __bfloat162float(h2));
    __nv_bfloat16 l3 = __float2bfloat16(v.w - __bfloat162float(h3));
    *(__nv_bfloat162*)(g_Ahi + (size_t)i * 4)     = __halves2bfloat162(h0, h1);
    *(__nv_bfloat162*)(g_Ahi + (size_t)i * 4 + 2) = __halves2bfloat162(h2, h3);
    *(__nv_bfloat162*)(g_Alo + (size_t)i * 4)     = __halves2bfloat162(l0, l1);
    *(__nv_bfloat162*)(g_Alo + (size_t)i * 4 + 2) = __halves2bfloat162(l2, l3);
}

// W stored transposed: g_Bhi[n][k] (n-major, K-contiguous) for the MMA B operand
__global__ void k_conv_w(const float* __restrict__ Wl1, const float* __restrict__ Wr1) {
    int i = blockIdx.x * blockDim.x + threadIdx.x;
    if (i >= 512 * 256) return;
    int n = i >> 8, k = i & 255;
    float v = (n < 256) ? Wl1[k * 256 + n] : Wr1[k * 256 + (n - 256)];
    __nv_bfloat16 h = __float2bfloat16(v);
    g_Bhi[n * 256 + k] = h;
    g_Blo[n * 256 + k] = __float2bfloat16(v - __bfloat162float(h));
}

// ---------------- CSR build (dst-sorted) ----------------
__global__ void k_hist(const int* __restrict__ ei) {
    int i = blockIdx.x * blockDim.x + threadIdx.x;
    if (i >= E2) return;
    int dd = (i < EE) ? ei[EE + i] : (i - EE);
    atomicAdd(&g_counts[dd], 1);
}

#define SCAN_BLOCKS 49

__global__ void k_scan1() {
    __shared__ int wsum[32];
    int tid = threadIdx.x;
    int lane = tid & 31, w = tid >> 5;
    int i = blockIdx.x * 1024 + tid;
    int v = (i < NN) ? g_counts[i] : 0;
    int x = v;
#pragma unroll
    for (int st = 1; st < 32; st <<= 1) {
        int y = __shfl_up_sync(0xffffffffu, x, st);
        if (lane >= st) x += y;
    }
    if (lane == 31) wsum[w] = x;
    __syncthreads();
    if (w == 0) {
        int s = wsum[lane];
#pragma unroll
        for (int st = 1; st < 32; st <<= 1) {
            int y = __shfl_up_sync(0xffffffffu, s, st);
            if (lane >= st) s += y;
        }
        wsum[lane] = s;
    }
    __syncthreads();
    int off = (w > 0) ? wsum[w - 1] : 0;
    int incl = x + off;
    if (i < NN) g_rowptr[i] = incl - v;
    if (tid == 1023) g_bsum[blockIdx.x] = incl;
}

__global__ void k_scan2() {
    if (threadIdx.x == 0) {
        int acc = 0;
        for (int b = 0; b < SCAN_BLOCKS; b++) { g_boff[b] = acc; acc += g_bsum[b]; }
        g_rowptr[NN] = acc;
    }
}

__global__ void k_scan3() {
    int i = blockIdx.x * 1024 + threadIdx.x;
    int off = g_boff[blockIdx.x];
    if (i < NN && blockIdx.x > 0) g_rowptr[i] += off;
}

__global__ void k_scatter(const int* __restrict__ ei) {
    int i = blockIdx.x * blockDim.x + threadIdx.x;
    if (i >= E2) return;
    int s  = (i < EE) ? ei[i]      : (i - EE);
    int dd = (i < EE) ? ei[EE + i] : (i - EE);
    int pos = g_rowptr[dd] + atomicAdd(&g_fill[dd], 1);
    g_esrc[pos] = s;
}

// ---------------- GEMM1 (mma.sync bf16 hi/lo): 3 accumulating passes ----------------
// block tile 128x128, warp tile 64x32 (2x4 warp grid), BK=64, 12 chunks.
// 3-stage cp.async pipeline in dynamic smem (108KB), one barrier per chunk.
#define KS 72             // bf16 elems per smem row (144B: 16B-aligned, conflict-free)
#define HALFSTAGE 18432   // 128*72*2 bytes (one operand tile)
#define STAGEB 36864      // A + B
#define GDYN (3 * STAGEB)

__global__ void __launch_bounds__(256) k_gemm1_mma() {
    extern __shared__ __align__(16) char dsm[];
    int t = threadIdx.x, lane = t & 31, w = t >> 5;
    int wm = w & 1, wn = w >> 1;
    int m0 = blockIdx.x * 128;
    int n0 = blockIdx.y * 128;
    uint32_t sbase = smem_u32(dsm);

    float acc[4][4][4];
#pragma unroll
    for (int i = 0; i < 4; i++)
#pragma unroll
        for (int j = 0; j < 4; j++)
#pragma unroll
            for (int q = 0; q < 4; q++) acc[i][j][q] = 0.f;

    // chunk c (0..11): pass = c/4 (0:AhiBhi 1:AloBhi 2:AhiBlo), kk = (c%4)*64
    auto issue_load = [&](int c) {
        int st = c % 3;
        int pass = c >> 2, kk = (c & 3) * 64;
        const __nv_bfloat16* Asrc = (pass == 1) ? g_Alo : g_Ahi;
        const __nv_bfloat16* Bsrc = (pass == 2) ? g_Blo : g_Bhi;
        uint32_t sa = sbase + st * STAGEB;
        uint32_t sb = sa + HALFSTAGE;
        // A tile: 128 rows x 64 bf16 = 8 granules/row -> 1024 granules, 4/thread
#pragma unroll
        for (int q = 0; q < 4; q++) {
            int idx = t + q * 256;
            int row = idx >> 3, gi = idx & 7;
            int gm = m0 + row;
            gm = gm < NN ? gm : NN - 1;
            cpa16(sa + row * 144 + gi * 16, Asrc + (size_t)gm * 256 + kk + gi * 8);
        }
#pragma unroll
        for (int q = 0; q < 4; q++) {
            int idx = t + q * 256;
            int row = idx >> 3, gi = idx & 7;
            cpa16(sb + row * 144 + gi * 16,
                  Bsrc + (size_t)(n0 + row) * 256 + kk + gi * 8);
        }
        asm volatile("cp.async.commit_group;" ::: "memory");
    };

    issue_load(0);
    issue_load(1);

    for (int c = 0; c < 12; c++) {
        cpwait<1>();
        __syncthreads();
        if (c + 2 < 12) issue_load(c + 2);  // stage (c-1)%3, last read at iter c-1
        uint32_t sa = sbase + (c % 3) * STAGEB;
        uint32_t sb = sa + HALFSTAGE;
#pragma unroll
        for (int ks = 0; ks < 4; ks++) {
            uint32_t a[4][4];
#pragma unroll
            for (int mf = 0; mf < 4; mf++) {
                uint32_t addr = sa + ((wm * 64 + mf * 16 + (lane & 15)) * KS +
                                      ks * 16 + (lane >> 4) * 8) *
                                         2;
                ldm4(a[mf], addr);
            }
            uint32_t b[2][4];
#pragma unroll
            for (int p = 0; p < 2; p++) {
                uint32_t addr =
                    sb + ((wn * 32 + p * 16 + (lane & 7) + ((lane >> 4) & 1) * 8) * KS +
                          ks * 16 + ((lane >> 3) & 1) * 8) *
                             2;
                ldm4(b[p], addr);
            }
#pragma unroll
            for (int mf = 0; mf < 4; mf++)
#pragma unroll
                for (int nf = 0; nf < 4; nf++) {
                    int p = nf >> 1, hi = (nf & 1) * 2;
                    mma16816(acc[mf][nf], a[mf], b[p][hi], b[p][hi + 1]);
                }
        }
    }

    // epilogue: add bias, write to g_xl1/g_xr1
#pragma unroll
    for (int mf = 0; mf < 4; mf++) {
        int row0 = m0 + wm * 64 + mf * 16 + (lane >> 2);
#pragma unroll
        for (int nf = 0; nf < 4; nf++) {
            int col = n0 + wn * 32 + nf * 8 + (lane & 3) * 2;
            float b0 = g_bcat1[col], b1 = g_bcat1[col + 1];
            float* base = (col < 256) ? g_xl1 : g_xr1;
            int cc = (col < 256) ? col : col - 256;
            if (row0 < NN) {
                float2 v = make_float2(acc[mf][nf][0] + b0, acc[mf][nf][1] + b1);
                *(float2*)(base + (size_t)row0 * 256 + cc) = v;
            }
            if (row0 + 8 < NN) {
                float2 v = make_float2(acc[mf][nf][2] + b0, acc[mf][nf][3] + b1);
                *(float2*)(base + (size_t)(row0 + 8) * 256 + cc) = v;
            }
        }
    }
}

// ---------------- layer-1 edge phase: warp per dst node, online softmax, 2-edge interleave ----------------
__global__ void __launch_bounds__(256) k_edge1(const float* __restrict__ att1,
                                               const float* __restrict__ bias1) {
    int gw = (blockIdx.x * blockDim.x + threadIdx.x) >> 5;
    int lane = threadIdx.x & 31;
    if (gw >= NN) return;
    int d = gw;
    int cb = lane * 8;  // 8 channels per lane; head = lane>>3
    const float4* xrp = (const float4*)(g_xr1 + (size_t)d * 256 + cb);
    float4 xr0 = xrp[0], xr1v = xrp[1];
    const float4* ap = (const float4*)(att1 + cb);
    float4 at0 = ap[0], at1 = ap[1];
    int p0 = g_rowptr[d], p1 = g_rowptr[d + 1];

    float m = -INFINITY, denom = 0.f;
    float4 acc0 = make_float4(0.f, 0.f, 0.f, 0.f), acc1 = acc0;

#define DOT8(r0, r1)                                                                \
    (lrelu((r0).x + xr0.x) * at0.x + lrelu((r0).y + xr0.y) * at0.y +                \
     lrelu((r0).z + xr0.z) * at0.z + lrelu((r0).w + xr0.w) * at0.w +                \
     lrelu((r1).x + xr1v.x) * at1.x + lrelu((r1).y + xr1v.y) * at1.y +              \
     lrelu((r1).z + xr1v.z) * at1.z + lrelu((r1).w + xr1v.w) * at1.w)

#define SMUP(pa, r0, r1)                                                            \
    do {                                                                            \
        if ((pa) > m) {                                                             \
            float sc_ = __expf(m - (pa));                                           \
            denom *= sc_;                                                           \
            acc0.x *= sc_; acc0.y *= sc_; acc0.z *= sc_; acc0.w *= sc_;             \
            acc1.x *= sc_; acc1.y *= sc_; acc1.z *= sc_; acc1.w *= sc_;             \
            m = (pa);                                                               \
        }                                                                           \
        float ee_ = __expf((pa)-m);                                                 \
        denom += ee_;                                                               \
        acc0.x += ee_ * (r0).x; acc0.y += ee_ * (r0).y;                             \
        acc0.z += ee_ * (r0).z; acc0.w += ee_ * (r0).w;                             \
        acc1.x += ee_ * (r1).x; acc1.y += ee_ * (r1).y;                             \
        acc1.z += ee_ * (r1).z; acc1.w += ee_ * (r1).w;                             \
    } while (0)

    int p = p0;
    float4 a0, a1, b0v, b1v;
    {
        int s = g_esrc[p];
        const float4* xs = (const float4*)(g_xl1 + (size_t)s * 256 + cb);
        a0 = xs[0]; a1 = xs[1];
    }
    if (p + 1 < p1) {
        int s = g_esrc[p + 1];
        const float4* xs = (const float4*)(g_xl1 + (size_t)s * 256 + cb);
        b0v = xs[0]; b1v = xs[1];
    }
    while (p + 1 < p1) {
        // prefetch next pair's rows (dummy-safe) before the reduce chains
        int s2 = g_esrc[(p + 2 < p1) ? p + 2 : p];
        int s3 = g_esrc[(p + 3 < p1) ? p + 3 : p];
        const float4* x2 = (const float4*)(g_xl1 + (size_t)s2 * 256 + cb);
        const float4* x3 = (const float4*)(g_xl1 + (size_t)s3 * 256 + cb);
        float4 n0 = x2[0], n1 = x2[1], n2 = x3[0], n3 = x3[1];

        float pa = DOT8(a0, a1);
        float pb = DOT8(b0v, b1v);
        pa += __shfl_xor_sync(0xffffffffu, pa, 1);
        pb += __shfl_xor_sync(0xffffffffu, pb, 1);
        pa += __shfl_xor_sync(0xffffffffu, pa, 2);
        pb += __shfl_xor_sync(0xffffffffu, pb, 2);
        pa += __shfl_xor_sync(0xffffffffu, pa, 4);
        pb += __shfl_xor_sync(0xffffffffu, pb, 4);

        SMUP(pa, a0, a1);
        SMUP(pb, b0v, b1v);

        a0 = n0; a1 = n1; b0v = n2; b1v = n3;
        p += 2;
    }
    if (p < p1) {
        float pa = DOT8(a0, a1);
        pa += __shfl_xor_sync(0xffffffffu, pa, 1);
        pa += __shfl_xor_sync(0xffffffffu, pa, 2);
        pa += __shfl_xor_sync(0xffffffffu, pa, 4);
        SMUP(pa, a0, a1);
    }
#undef DOT8
#undef SMUP

    float inv = 1.f / (denom + 1e-16f);
    const float4* bp = (const float4*)(bias1 + cb);
    float4 b0 = bp[0], b1 = bp[1];
    float4 o0, o1;
    o0.x = tanhf(acc0.x * inv + b0.x); o0.y = tanhf(acc0.y * inv + b0.y);
    o0.z = tanhf(acc0.z * inv + b0.z); o0.w = tanhf(acc0.w * inv + b0.w);
    o1.x = tanhf(acc1.x * inv + b1.x); o1.y = tanhf(acc1.y * inv + b1.y);
    o1.z = tanhf(acc1.z * inv + b1.z); o1.w = tanhf(acc1.w * inv + b1.w);
    float4* hp = (float4*)(g_h1 + (size_t)d * 256 + cb);
    hp[0] = o0; hp[1] = o1;
}

// ---------------- GEMM2 ----------------
__global__ void k_gemm2() {
    __shared__ float Ws[256 * 32];
    int t = threadIdx.x;
    for (int i = t; i < 256 * 32; i += 256) Ws[i] = g_Wcat2[i];
    __syncthreads();
    int warp = t >> 5, lane = t & 31;
    int row = blockIdx.x * 8 + warp;
    if (row >= NN) return;
    float acc = 0.f;
    const float* hrow = g_h1 + (size_t)row * 256;
    for (int k0 = 0; k0 < 256; k0 += 32) {
        float hv = hrow[k0 + lane];
#pragma unroll
        for (int j = 0; j < 32; j++) {
            float hb = __shfl_sync(0xffffffffu, hv, j);
            acc += hb * Ws[(k0 + j) * 32 + lane];
        }
    }
    float v = acc + g_bcat2[lane];
    if (lane < 16) g_xl2[(size_t)row * 16 + lane] = v;
    else           g_xr2[(size_t)row * 16 + (lane - 16)] = v;
}

// ---------------- layer-2 edge phase + log_softmax: online softmax, pipelined ----------------
__global__ void __launch_bounds__(256) k_edge2(const float* __restrict__ att2,
                                               const float* __restrict__ bias2,
                                               float* __restrict__ outO,
                                               float* __restrict__ outLP) {
    int gw = (blockIdx.x * blockDim.x + threadIdx.x) >> 5;
    int lane = threadIdx.x & 31;
    if (gw >= NN) return;
    int d = gw;
    int c = lane & 15;  // both 16-lane halves mirror the same work
    float xrv = g_xr2[(size_t)d * 16 + c];
    float av = att2[c];
    int p0 = g_rowptr[d], p1 = g_rowptr[d + 1];

    float m = -INFINITY, denom = 0.f, acc = 0.f;

    int s = g_esrc[p0];
    float xv = g_xl2[(size_t)s * 16 + c];

    for (int p = p0; p < p1; p++) {
        float cx = xv;
        if (p + 1 < p1) {
            int s2 = g_esrc[p + 1];
            xv = g_xl2[(size_t)s2 * 16 + c];
        }
        float v = cx + xrv;
        v = v > 0.f ? v : 0.2f * v;
        float pa = v * av;
        pa += __shfl_xor_sync(0xffffffffu, pa, 1);
        pa += __shfl_xor_sync(0xffffffffu, pa, 2);
        pa += __shfl_xor_sync(0xffffffffu, pa, 4);
        pa += __shfl_xor_sync(0xffffffffu, pa, 8);
        if (pa > m) {
            float sc = __expf(m - pa);
            denom *= sc;
            acc *= sc;
            m = pa;
        }
        float ee = __expf(pa - m);
        denom += ee;
        acc += ee * cx;
    }
    float o = acc / (denom + 1e-16f) + bias2[c];

    // log_softmax over the 16 channels (within each 16-lane half)
    float mm = o;
    mm = fmaxf(mm, __shfl_xor_sync(0xffffffffu, mm, 1));
    mm = fmaxf(mm, __shfl_xor_sync(0xffffffffu, mm, 2));
    mm = fmaxf(mm, __shfl_xor_sync(0xffffffffu, mm, 4));
    mm = fmaxf(mm, __shfl_xor_sync(0xffffffffu, mm, 8));
    float se = __expf(o - mm);
    se += __shfl_xor_sync(0xffffffffu, se, 1);
    se += __shfl_xor_sync(0xffffffffu, se, 2);
    se += __shfl_xor_sync(0xffffffffu, se, 4);
    se += __shfl_xor_sync(0xffffffffu, se, 8);
    float lp = o - mm - logf(se);

    if (lane < 16) {
        outO[(size_t)d * 16 + c] = o;
        if (outLP) outLP[(size_t)d * 16 + c] = lp;
    }
}

// ---------------- launch ----------------
extern "C" void kernel_launch(void* const* d_in, const int* in_sizes, int n_in,
                              void* d_out, int out_size) {
    const float* x     = (const float*)d_in[0];
    const int*   ei    = (const int*)d_in[1];
    const float* Wl1   = (const float*)d_in[2];
    const float* bl1   = (const float*)d_in[3];
    const float* Wr1   = (const float*)d_in[4];
    const float* br1   = (const float*)d_in[5];
    const float* att1  = (const float*)d_in[6];
    const float* bias1 = (const float*)d_in[7];
    const float* Wl2   = (const float*)d_in[8];
    const float* bl2   = (const float*)d_in[9];
    const float* Wr2   = (const float*)d_in[10];
    const float* br2   = (const float*)d_in[11];
    const float* att2  = (const float*)d_in[12];
    const float* bias2 = (const float*)d_in[13];

    float* outO  = (float*)d_out;
    float* outLP = (out_size >= 2 * NN * OUTD) ? ((float*)d_out + NN * OUTD) : nullptr;

    cudaFuncSetAttribute(k_gemm1_mma, cudaFuncAttributeMaxDynamicSharedMemorySize,
                         GDYN);

    // GEMM1 deps first so k_gemm1_mma lands at the profiled slot.
    k_conv_x<<<(NN * 64 + 255) / 256, 256>>>(x);
    k_conv_w<<<512, 256>>>(Wl1, Wr1);
    k_prep<<<32, 256>>>(bl1, br1, Wl2, bl2, Wr2, br2);
    dim3 g1(MTILES, 4);
    k_gemm1_mma<<<g1, 256, GDYN>>>();

    k_zero<<<(NN + 255) / 256, 256>>>();
    k_hist<<<(E2 + 255) / 256, 256>>>(ei);
    k_scan1<<<SCAN_BLOCKS, 1024>>>();
    k_scan2<<<1, 32>>>();
    k_scan3<<<SCAN_BLOCKS, 1024>>>();
    k_scatter<<<(E2 + 255) / 256, 256>>>(ei);

    k_edge1<<<(NN + 7) / 8, 256>>>(att1, bias1);
    k_gemm2<<<(NN + 7) / 8, 256>>>();
    k_edge2<<<(NN + 7) / 8, 256>>>(att2, bias2, outO, outLP);
}